// round 2
// baseline (speedup 1.0000x reference)
#include <cuda_runtime.h>

// Problem constants (GraphTransformerLayer: N=50000 nodes, E=800000 edges, D=128, H=8, HD=16)
static constexpr int NNODE = 50000;
static constexpr int NEDGE = 800000;
static constexpr int D     = 128;

// ---------------------------------------------------------------------------
// Scratch (device globals; ~1.85 GB total; accumulators reset every launch)
// ---------------------------------------------------------------------------
__device__ float  g_Q [NNODE * D];
__device__ float  g_K [NNODE * D];
__device__ float  g_V [NNODE * D];
__device__ float  g_ssum[NNODE * D];     // softmax denominators (atomic accum)
__device__ float  g_wV [NNODE * D];      // aggregated alpha*V (atomic accum)
__device__ float  g_h1 [NNODE * D];      // h1 raw (pre-BN1)
__device__ float  g_hh [NNODE * 2 * D];  // h FFN hidden
__device__ float  g_score[(size_t)NEDGE * D];      // pe, then full score
__device__ float  g_e1 [(size_t)NEDGE * D];        // e1 raw (pre-BN1)
__device__ float  g_eh [(size_t)NEDGE * 2 * D];    // e FFN hidden
__device__ double g_stat[4 * 2 * 128];   // [set][sum|sumsq][128]
__device__ float  g_bnsc[4 * 128];       // per-set BN scale  (gamma*rsig)
__device__ float  g_bnsh[4 * 128];       // per-set BN shift  (beta - mu*scale)

// ---------------------------------------------------------------------------
// Generic FP32 GEMM: C[M,Nout] = A[M,KD] @ B[KD,Nout] (+bias)(+residual)(+BN)(relu)(stats)
// Tile 128x128, 256 threads, 16x4 microtile, K-step 16.
// ---------------------------------------------------------------------------
enum { M_RELU = 1, M_RESP = 2, M_RESBN = 4, M_STATS = 8, M_ABN = 16 };

template <int KD, int MODE>
__global__ __launch_bounds__(256) void gemm_kernel(
    const float* __restrict__ A,
    const float* __restrict__ B, int ldb,
    float* __restrict__ C, int ldc,
    const float* __restrict__ bias,                    // nullable
    const float* __restrict__ resid, int ldr,          // used by RESP/RESBN
    const float* __restrict__ tsc, const float* __restrict__ tsh,  // BN scale/shift (ABN or RESBN)
    double* __restrict__ stat,                         // [sum[128], sumsq[128]]
    int M)
{
    __shared__ float As[16][128];
    __shared__ float Bs[16][128];
    __shared__ float red[2][128];

    const int tid = threadIdx.x;
    const int tx  = tid & 31;
    const int ty  = tid >> 5;
    const int m0  = blockIdx.y * 128;
    const int nb  = blockIdx.x * 128;
    const float* Bp = B + nb;

    float acc[16][4];
#pragma unroll
    for (int i = 0; i < 16; i++) { acc[i][0]=0.f; acc[i][1]=0.f; acc[i][2]=0.f; acc[i][3]=0.f; }

    const int arow = tid >> 2;
    const int aq   = (tid & 3) << 2;
    const int brow = tid >> 5;
    const int bcol = (tid & 31) << 2;

    for (int k0 = 0; k0 < KD; k0 += 16) {
        if (k0) __syncthreads();
#pragma unroll
        for (int r = 0; r < 2; r++) {
            int m  = arow + r * 64;
            int gm = m0 + m;
            float4 v = make_float4(0.f, 0.f, 0.f, 0.f);
            if (gm < M) {
                v = *(const float4*)(A + (size_t)gm * KD + k0 + aq);
                if (MODE & M_ABN) {
                    int c = k0 + aq;
                    v.x = v.x * tsc[c+0] + tsh[c+0];
                    v.y = v.y * tsc[c+1] + tsh[c+1];
                    v.z = v.z * tsc[c+2] + tsh[c+2];
                    v.w = v.w * tsc[c+3] + tsh[c+3];
                }
            }
            As[aq+0][m] = v.x; As[aq+1][m] = v.y; As[aq+2][m] = v.z; As[aq+3][m] = v.w;
        }
#pragma unroll
        for (int r = 0; r < 2; r++) {
            int k = brow + r * 8;
            *(float4*)&Bs[k][bcol] = *(const float4*)(Bp + (size_t)(k0 + k) * ldb + bcol);
        }
        __syncthreads();
#pragma unroll
        for (int k = 0; k < 16; k++) {
            float4 b4 = *(float4*)&Bs[k][tx << 2];
#pragma unroll
            for (int i = 0; i < 16; i++) {
                float a = As[k][ty + (i << 3)];
                acc[i][0] += a * b4.x; acc[i][1] += a * b4.y;
                acc[i][2] += a * b4.z; acc[i][3] += a * b4.w;
            }
        }
    }

    // Epilogue
    const int nl = tx << 2;
    float b0 = 0.f, b1 = 0.f, b2 = 0.f, b3 = 0.f;
    if (bias) { b0 = bias[nb+nl]; b1 = bias[nb+nl+1]; b2 = bias[nb+nl+2]; b3 = bias[nb+nl+3]; }
    float csum[4] = {0.f,0.f,0.f,0.f}, csq[4] = {0.f,0.f,0.f,0.f};
#pragma unroll
    for (int i = 0; i < 16; i++) {
        int gm = m0 + ty + (i << 3);
        if (gm >= M) continue;
        float4 v = make_float4(acc[i][0]+b0, acc[i][1]+b1, acc[i][2]+b2, acc[i][3]+b3);
        if (MODE & M_RESP) {
            float4 r = *(const float4*)(resid + (size_t)gm * ldr + nb + nl);
            v.x += r.x; v.y += r.y; v.z += r.z; v.w += r.w;
        }
        if (MODE & M_RESBN) {
            float4 r = *(const float4*)(resid + (size_t)gm * ldr + nb + nl);
            int c = nb + nl;
            v.x += r.x * tsc[c+0] + tsh[c+0];
            v.y += r.y * tsc[c+1] + tsh[c+1];
            v.z += r.z * tsc[c+2] + tsh[c+2];
            v.w += r.w * tsc[c+3] + tsh[c+3];
        }
        if (MODE & M_RELU) {
            v.x = fmaxf(v.x, 0.f); v.y = fmaxf(v.y, 0.f);
            v.z = fmaxf(v.z, 0.f); v.w = fmaxf(v.w, 0.f);
        }
        *(float4*)(C + (size_t)gm * ldc + nb + nl) = v;
        if (MODE & M_STATS) {
            csum[0] += v.x; csum[1] += v.y; csum[2] += v.z; csum[3] += v.w;
            csq[0] += v.x*v.x; csq[1] += v.y*v.y; csq[2] += v.z*v.z; csq[3] += v.w*v.w;
        }
    }
    if (MODE & M_STATS) {
        __syncthreads();
        if (tid < 128) { red[0][tid] = 0.f; red[1][tid] = 0.f; }
        __syncthreads();
#pragma unroll
        for (int j = 0; j < 4; j++) {
            atomicAdd(&red[0][nl + j], csum[j]);
            atomicAdd(&red[1][nl + j], csq[j]);
        }
        __syncthreads();
        if (tid < 128) {
            atomicAdd(&stat[tid],       (double)red[0][tid]);
            atomicAdd(&stat[128 + tid], (double)red[1][tid]);
        }
    }
}

// ---------------------------------------------------------------------------
// Edge kernels: one warp per edge; lane handles channels [4*lane, 4*lane+4)
// head(c) = c/16 == lane/4, so the per-head K·Q dot reduces over 4-lane groups.
// Softmax without max-shift (scores bounded ~|2|, shift-invariant).
// ---------------------------------------------------------------------------
__global__ void edge_score_kernel(const float* __restrict__ Q, const float* __restrict__ K,
                                  float* __restrict__ score, float* __restrict__ ssum,
                                  const int* __restrict__ src, const int* __restrict__ dst, int E)
{
    int eid  = (int)((blockIdx.x * (size_t)blockDim.x + threadIdx.x) >> 5);
    int lane = threadIdx.x & 31;
    if (eid >= E) return;
    int s = src[eid], d = dst[eid];
    float4 kk = *(const float4*)(K + (size_t)s * D + (lane << 2));
    float4 qq = *(const float4*)(Q + (size_t)d * D + (lane << 2));
    float p = kk.x*qq.x + kk.y*qq.y + kk.z*qq.z + kk.w*qq.w;
    p += __shfl_xor_sync(0xffffffffu, p, 1);
    p += __shfl_xor_sync(0xffffffffu, p, 2);   // dot over the 16 channels of this head
    float dt = p * 0.25f;                      // / sqrt(HD=16)
    size_t off = (size_t)eid * D + (lane << 2);
    float4 pe = *(const float4*)(score + off);
    float4 sc = make_float4(pe.x + dt, pe.y + dt, pe.z + dt, pe.w + dt);
    *(float4*)(score + off) = sc;
    float4 ex = make_float4(__expf(sc.x), __expf(sc.y), __expf(sc.z), __expf(sc.w));
    float* sp = ssum + (size_t)d * D + (lane << 2);
    atomicAdd(sp + 0, ex.x); atomicAdd(sp + 1, ex.y);
    atomicAdd(sp + 2, ex.z); atomicAdd(sp + 3, ex.w);
}

__global__ void edge_agg_kernel(const float* __restrict__ V, const float* __restrict__ score,
                                const float* __restrict__ ssum, float* __restrict__ wV,
                                const int* __restrict__ src, const int* __restrict__ dst, int E)
{
    int eid  = (int)((blockIdx.x * (size_t)blockDim.x + threadIdx.x) >> 5);
    int lane = threadIdx.x & 31;
    if (eid >= E) return;
    int s = src[eid], d = dst[eid];
    size_t off = (size_t)eid * D + (lane << 2);
    float4 sc = *(const float4*)(score + off);
    float4 ss = *(const float4*)(ssum + (size_t)d * D + (lane << 2));
    float4 vv = *(const float4*)(V + (size_t)s * D + (lane << 2));
    float a0 = __expf(sc.x) / ss.x * vv.x;
    float a1 = __expf(sc.y) / ss.y * vv.y;
    float a2 = __expf(sc.z) / ss.z * vv.z;
    float a3 = __expf(sc.w) / ss.w * vv.w;
    float* wp = wV + (size_t)d * D + (lane << 2);
    atomicAdd(wp + 0, a0); atomicAdd(wp + 1, a1);
    atomicAdd(wp + 2, a2); atomicAdd(wp + 3, a3);
}

// ---------------------------------------------------------------------------
// BN stat finalize + apply
// ---------------------------------------------------------------------------
__global__ void bn_finalize_kernel(const double* __restrict__ stat,
                                   const float* __restrict__ gamma, const float* __restrict__ beta,
                                   float* __restrict__ osc, float* __restrict__ osh, double invM)
{
    int c = threadIdx.x;
    float mu  = (float)(stat[c] * invM);
    float var = (float)(stat[128 + c] * invM) - mu * mu;
    float rs  = rsqrtf(var + 1e-5f);
    float scv = gamma[c] * rs;
    osc[c] = scv;
    osh[c] = beta[c] - mu * scv;
}

__global__ void bn_apply_kernel(float* __restrict__ x, const float* __restrict__ sc,
                                const float* __restrict__ sh, long n4)
{
    long i = (long)blockIdx.x * blockDim.x + threadIdx.x;
    if (i >= n4) return;
    float4 v = ((float4*)x)[i];
    int c = (int)(i & 31) << 2;
    v.x = v.x * sc[c+0] + sh[c+0];
    v.y = v.y * sc[c+1] + sh[c+1];
    v.z = v.z * sc[c+2] + sh[c+2];
    v.w = v.w * sc[c+3] + sh[c+3];
    ((float4*)x)[i] = v;
}

// ---------------------------------------------------------------------------
// Launch
// ---------------------------------------------------------------------------
extern "C" void kernel_launch(void* const* d_in, const int* in_sizes, int n_in,
                              void* d_out, int out_size)
{
    const float* h    = (const float*)d_in[0];
    const float* e    = (const float*)d_in[1];
    const int*   src  = (const int*)d_in[2];
    const int*   dst  = (const int*)d_in[3];
    const float* Wq   = (const float*)d_in[4];
    const float* Wk   = (const float*)d_in[5];
    const float* Wv   = (const float*)d_in[6];
    const float* We   = (const float*)d_in[7];
    const float* Ohw  = (const float*)d_in[8];
    const float* Ohb  = (const float*)d_in[9];
    const float* Oew  = (const float*)d_in[10];
    const float* Oeb  = (const float*)d_in[11];
    const float* bn1hg = (const float*)d_in[12];
    const float* bn1hb = (const float*)d_in[13];
    const float* bn1eg = (const float*)d_in[14];
    const float* bn1eb = (const float*)d_in[15];
    const float* bn2hg = (const float*)d_in[16];
    const float* bn2hb = (const float*)d_in[17];
    const float* bn2eg = (const float*)d_in[18];
    const float* bn2eb = (const float*)d_in[19];
    const float* f1hw = (const float*)d_in[20];
    const float* f1hb = (const float*)d_in[21];
    const float* f2hw = (const float*)d_in[22];
    const float* f2hb = (const float*)d_in[23];
    const float* f1ew = (const float*)d_in[24];
    const float* f1eb = (const float*)d_in[25];
    const float* f2ew = (const float*)d_in[26];
    const float* f2eb = (const float*)d_in[27];

    const int Nn = in_sizes[0] / D;   // 50000
    const int Ne = in_sizes[2];       // 800000

    float* out   = (float*)d_out;
    float* out_h = out;
    float* out_e = out + (size_t)Nn * D;

    void* pv;
    cudaGetSymbolAddress(&pv, g_Q);     float* Q  = (float*)pv;
    cudaGetSymbolAddress(&pv, g_K);     float* Kk = (float*)pv;
    cudaGetSymbolAddress(&pv, g_V);     float* V  = (float*)pv;
    cudaGetSymbolAddress(&pv, g_ssum);  float* SS = (float*)pv;
    cudaGetSymbolAddress(&pv, g_wV);    float* WV = (float*)pv;
    cudaGetSymbolAddress(&pv, g_h1);    float* H1 = (float*)pv;
    cudaGetSymbolAddress(&pv, g_hh);    float* HH = (float*)pv;
    cudaGetSymbolAddress(&pv, g_score); float* SC = (float*)pv;
    cudaGetSymbolAddress(&pv, g_e1);    float* E1 = (float*)pv;
    cudaGetSymbolAddress(&pv, g_eh);    float* EH = (float*)pv;
    cudaGetSymbolAddress(&pv, g_stat);  double* ST = (double*)pv;
    cudaGetSymbolAddress(&pv, g_bnsc);  float* BSC = (float*)pv;
    cudaGetSymbolAddress(&pv, g_bnsh);  float* BSH = (float*)pv;

    // Reset accumulators (replayed every graph launch)
    cudaMemsetAsync(SS, 0, sizeof(float) * (size_t)Nn * D);
    cudaMemsetAsync(WV, 0, sizeof(float) * (size_t)Nn * D);
    cudaMemsetAsync(ST, 0, sizeof(double) * 4 * 2 * 128);

    dim3 blk(256);
    dim3 gN (1, (Nn + 127) / 128);
    dim3 gE (1, (Ne + 127) / 128);
    dim3 gN2(2, (Nn + 127) / 128);
    dim3 gE2(2, (Ne + 127) / 128);

    // 1) Projections
    gemm_kernel<128, 0><<<gN, blk>>>(h, Wq, 128, Q,  128, nullptr, nullptr, 0, nullptr, nullptr, nullptr, Nn);
    gemm_kernel<128, 0><<<gN, blk>>>(h, Wk, 128, Kk, 128, nullptr, nullptr, 0, nullptr, nullptr, nullptr, Nn);
    gemm_kernel<128, 0><<<gN, blk>>>(h, Wv, 128, V,  128, nullptr, nullptr, 0, nullptr, nullptr, nullptr, Nn);
    gemm_kernel<128, 0><<<gE, blk>>>(e, We, 128, SC, 128, nullptr, nullptr, 0, nullptr, nullptr, nullptr, Ne);

    // 2) Edge attention: score = pe + dot/4; accumulate exp-sums; aggregate alpha*V
    int eblocks = (int)(((size_t)Ne * 32 + 255) / 256);
    edge_score_kernel<<<eblocks, 256>>>(Q, Kk, SC, SS, src, dst, Ne);
    edge_agg_kernel  <<<eblocks, 256>>>(V, SC, SS, WV, src, dst, Ne);

    // 3) Output projections + residual; accumulate BN1 stats
    gemm_kernel<128, M_RESP | M_STATS><<<gN, blk>>>(WV, Ohw, 128, H1, 128, Ohb, h, 128, nullptr, nullptr, ST + 0 * 256, Nn);
    gemm_kernel<128, M_RESP | M_STATS><<<gE, blk>>>(SC, Oew, 128, E1, 128, Oeb, e, 128, nullptr, nullptr, ST + 1 * 256, Ne);

    bn_finalize_kernel<<<1, 128>>>(ST + 0 * 256, bn1hg, bn1hb, BSC + 0 * 128, BSH + 0 * 128, 1.0 / Nn);
    bn_finalize_kernel<<<1, 128>>>(ST + 1 * 256, bn1eg, bn1eb, BSC + 1 * 128, BSH + 1 * 128, 1.0 / Ne);

    // 4) FFN layer 1: relu(bn1(x) @ f1 + b1), BN applied in A-load path
    gemm_kernel<128, M_ABN | M_RELU><<<gN2, blk>>>(H1, f1hw, 256, HH, 256, f1hb, nullptr, 0, BSC + 0 * 128, BSH + 0 * 128, nullptr, Nn);
    gemm_kernel<128, M_ABN | M_RELU><<<gE2, blk>>>(E1, f1ew, 256, EH, 256, f1eb, nullptr, 0, BSC + 1 * 128, BSH + 1 * 128, nullptr, Ne);

    // 5) FFN layer 2 + residual bn1(x); accumulate BN2 stats; write raw into out
    gemm_kernel<256, M_RESBN | M_STATS><<<gN, blk>>>(HH, f2hw, 128, out_h, 128, f2hb, H1, 128, BSC + 0 * 128, BSH + 0 * 128, ST + 2 * 256, Nn);
    gemm_kernel<256, M_RESBN | M_STATS><<<gE, blk>>>(EH, f2ew, 128, out_e, 128, f2eb, E1, 128, BSC + 1 * 128, BSH + 1 * 128, ST + 3 * 256, Ne);

    bn_finalize_kernel<<<1, 128>>>(ST + 2 * 256, bn2hg, bn2hb, BSC + 2 * 128, BSH + 2 * 128, 1.0 / Nn);
    bn_finalize_kernel<<<1, 128>>>(ST + 3 * 256, bn2eg, bn2eb, BSC + 3 * 128, BSH + 3 * 128, 1.0 / Ne);

    // 6) BN2 apply in-place on output
    long n4h = (long)Nn * D / 4;
    long n4e = (long)Ne * D / 4;
    bn_apply_kernel<<<(int)((n4h + 255) / 256), 256>>>(out_h, BSC + 2 * 128, BSH + 2 * 128, n4h);
    bn_apply_kernel<<<(int)((n4e + 255) / 256), 256>>>(out_e, BSC + 3 * 128, BSH + 3 * 128, n4e);
}

// round 5
// speedup vs baseline: 2.3283x; 2.3283x over previous
#include <cuda_runtime.h>
#include <cstdint>

// Problem constants (GraphTransformerLayer: N=50000 nodes, E=800000 edges, D=128, H=8, HD=16)
static constexpr int NNODE = 50000;
static constexpr int NEDGE = 800000;
static constexpr int D     = 128;

// ---------------------------------------------------------------------------
// Scratch (device globals; accumulators reset every launch)
// ---------------------------------------------------------------------------
__device__ float  g_Q [NNODE * D];
__device__ float  g_K [NNODE * D];
__device__ float  g_V [NNODE * D];
__device__ float  g_ssum[NNODE * D];
__device__ float  g_wV [NNODE * D];
__device__ float  g_h1 [NNODE * D];
__device__ float  g_hh [NNODE * 2 * D];
__device__ float  g_score[(size_t)NEDGE * D];
__device__ float  g_e1 [(size_t)NEDGE * D];
__device__ float  g_eh [(size_t)NEDGE * 2 * D];
__device__ double g_stat[4 * 2 * 128];
__device__ float  g_bnsc[4 * 128];
__device__ float  g_bnsh[4 * 128];

enum { M_RELU = 1, M_RESP = 2, M_RESBN = 4, M_STATS = 8, M_ABN = 16 };

__device__ __forceinline__ uint32_t f2tf(float f) {
    uint32_t u;
    asm("cvt.rna.tf32.f32 %0, %1;" : "=r"(u) : "f"(f));
    return u;
}

__device__ __forceinline__ void mma_tf32(float* c, const uint32_t* a, const uint32_t* b) {
    asm volatile(
        "mma.sync.aligned.m16n8k8.row.col.f32.tf32.tf32.f32 "
        "{%0,%1,%2,%3},{%4,%5,%6,%7},{%8,%9},{%0,%1,%2,%3};"
        : "+f"(c[0]), "+f"(c[1]), "+f"(c[2]), "+f"(c[3])
        : "r"(a[0]), "r"(a[1]), "r"(a[2]), "r"(a[3]), "r"(b[0]), "r"(b[1]));
}

// ---------------------------------------------------------------------------
// Tensor-core GEMM: C[M,Nout] = A[M,KD] @ B[KD,Nout] (+bias)(+res)(+BN)(relu)(stats)
// Block tile 128x128, 256 threads (8 warps, warp tile 32x64), K-step 16.
// A staged stride 20 (conflict-free frag loads), B staged stride 136.
// ---------------------------------------------------------------------------
template <int KD, int MODE>
__global__ __launch_bounds__(256, 2) void gemm_tc(
    const float* __restrict__ A,
    const float* __restrict__ B, int ldb,
    float* __restrict__ C, int ldc,
    const float* __restrict__ bias,
    const float* __restrict__ resid, int ldr,
    const float* __restrict__ tsc, const float* __restrict__ tsh,
    double* __restrict__ stat,
    int M)
{
    __shared__ uint32_t As[128 * 20];
    __shared__ uint32_t Bs[16 * 136];
    __shared__ float red[2][128];

    const int tid  = threadIdx.x;
    const int lane = tid & 31;
    const int warp = tid >> 5;
    const int g    = lane >> 2;
    const int tig  = lane & 3;
    const int wm   = (warp & 3) * 32;   // warp m offset in block
    const int wn   = (warp >> 2) * 64;  // warp n offset in block
    const int m0   = blockIdx.y * 128;
    const int nb   = blockIdx.x * 128;

    float acc[2][8][4];
#pragma unroll
    for (int mt = 0; mt < 2; mt++)
#pragma unroll
        for (int nt = 0; nt < 8; nt++) {
            acc[mt][nt][0] = 0.f; acc[mt][nt][1] = 0.f;
            acc[mt][nt][2] = 0.f; acc[mt][nt][3] = 0.f;
        }

    const int arow = tid >> 2;          // 0..63
    const int aq   = (tid & 3) << 2;    // 0,4,8,12
    const int brow = tid >> 5;          // 0..7
    const int bcol = lane << 2;         // 0..124

    for (int k0 = 0; k0 < KD; k0 += 16) {
        if (k0) __syncthreads();
        // stage A: 128 rows x 16 cols (tf32 bits), row stride 20
#pragma unroll
        for (int r = 0; r < 2; r++) {
            int m  = arow + r * 64;
            int gm = m0 + m;
            float4 v = make_float4(0.f, 0.f, 0.f, 0.f);
            if (gm < M) {
                v = *(const float4*)(A + (size_t)gm * KD + k0 + aq);
                if (MODE & M_ABN) {
                    int c = k0 + aq;
                    v.x = v.x * tsc[c+0] + tsh[c+0];
                    v.y = v.y * tsc[c+1] + tsh[c+1];
                    v.z = v.z * tsc[c+2] + tsh[c+2];
                    v.w = v.w * tsc[c+3] + tsh[c+3];
                }
            }
            uint4 t = make_uint4(f2tf(v.x), f2tf(v.y), f2tf(v.z), f2tf(v.w));
            *(uint4*)&As[m * 20 + aq] = t;
        }
        // stage B: 16 rows x 128 cols, row stride 136
#pragma unroll
        for (int r = 0; r < 2; r++) {
            int k = brow + r * 8;
            float4 v = *(const float4*)(B + (size_t)(k0 + k) * ldb + nb + bcol);
            uint4 t = make_uint4(f2tf(v.x), f2tf(v.y), f2tf(v.z), f2tf(v.w));
            *(uint4*)&Bs[k * 136 + bcol] = t;
        }
        __syncthreads();

#pragma unroll
        for (int kk = 0; kk < 16; kk += 8) {
            uint32_t af[2][4], bf[8][2];
#pragma unroll
            for (int mt = 0; mt < 2; mt++) {
                int rm = wm + mt * 16;
                af[mt][0] = As[(rm + g)     * 20 + kk + tig];
                af[mt][1] = As[(rm + g + 8) * 20 + kk + tig];
                af[mt][2] = As[(rm + g)     * 20 + kk + tig + 4];
                af[mt][3] = As[(rm + g + 8) * 20 + kk + tig + 4];
            }
#pragma unroll
            for (int nt = 0; nt < 8; nt++) {
                int cn = wn + nt * 8 + g;
                bf[nt][0] = Bs[(kk + tig)     * 136 + cn];
                bf[nt][1] = Bs[(kk + tig + 4) * 136 + cn];
            }
#pragma unroll
            for (int mt = 0; mt < 2; mt++)
#pragma unroll
                for (int nt = 0; nt < 8; nt++)
                    mma_tf32(acc[mt][nt], af[mt], bf[nt]);
        }
    }

    // ---------------- Epilogue ----------------
    const int cbase = wn + (tig << 1);  // channel pair base within block
    float s[8][2], q[8][2];
#pragma unroll
    for (int nt = 0; nt < 8; nt++) { s[nt][0]=0.f; s[nt][1]=0.f; q[nt][0]=0.f; q[nt][1]=0.f; }

#pragma unroll
    for (int mt = 0; mt < 2; mt++) {
        int r0 = m0 + wm + mt * 16 + g;
#pragma unroll
        for (int half = 0; half < 2; half++) {
            int gm = r0 + half * 8;
            if (gm >= M) continue;
#pragma unroll
            for (int nt = 0; nt < 8; nt++) {
                int c = nb + cbase + nt * 8;
                float x0 = acc[mt][nt][half * 2 + 0];
                float x1 = acc[mt][nt][half * 2 + 1];
                if (bias) { x0 += bias[c]; x1 += bias[c + 1]; }
                if (MODE & M_RESP) {
                    float2 rr = *(const float2*)(resid + (size_t)gm * ldr + c);
                    x0 += rr.x; x1 += rr.y;
                }
                if (MODE & M_RESBN) {
                    float2 rr = *(const float2*)(resid + (size_t)gm * ldr + c);
                    x0 += rr.x * tsc[c] + tsh[c];
                    x1 += rr.y * tsc[c + 1] + tsh[c + 1];
                }
                if (MODE & M_RELU) { x0 = fmaxf(x0, 0.f); x1 = fmaxf(x1, 0.f); }
                *(float2*)(C + (size_t)gm * ldc + c) = make_float2(x0, x1);
                if (MODE & M_STATS) {
                    s[nt][0] += x0; s[nt][1] += x1;
                    q[nt][0] += x0 * x0; q[nt][1] += x1 * x1;
                }
            }
        }
    }

    if (MODE & M_STATS) {
        __syncthreads();
        if (tid < 128) { red[0][tid] = 0.f; red[1][tid] = 0.f; }
        __syncthreads();
#pragma unroll
        for (int nt = 0; nt < 8; nt++) {
            int c = cbase + nt * 8;   // STATS modes always have Nout=128, nb=0
            atomicAdd(&red[0][c],     s[nt][0]);
            atomicAdd(&red[0][c + 1], s[nt][1]);
            atomicAdd(&red[1][c],     q[nt][0]);
            atomicAdd(&red[1][c + 1], q[nt][1]);
        }
        __syncthreads();
        if (tid < 128) {
            atomicAdd(&stat[tid],       (double)red[0][tid]);
            atomicAdd(&stat[128 + tid], (double)red[1][tid]);
        }
    }
}

// ---------------------------------------------------------------------------
// Edge kernels: one warp per edge; lane handles channels [4*lane, 4*lane+4)
// Softmax without max-shift (scores bounded, shift-invariant).
// ---------------------------------------------------------------------------
__global__ void edge_score_kernel(const float* __restrict__ Q, const float* __restrict__ K,
                                  float* __restrict__ score, float* __restrict__ ssum,
                                  const int* __restrict__ src, const int* __restrict__ dst, int E)
{
    int eid  = (int)((blockIdx.x * (size_t)blockDim.x + threadIdx.x) >> 5);
    int lane = threadIdx.x & 31;
    if (eid >= E) return;
    int s = src[eid], d = dst[eid];
    float4 kk = *(const float4*)(K + (size_t)s * D + (lane << 2));
    float4 qq = *(const float4*)(Q + (size_t)d * D + (lane << 2));
    float p = kk.x*qq.x + kk.y*qq.y + kk.z*qq.z + kk.w*qq.w;
    p += __shfl_xor_sync(0xffffffffu, p, 1);
    p += __shfl_xor_sync(0xffffffffu, p, 2);   // dot over the 16 channels of this head
    float dt = p * 0.25f;                      // / sqrt(HD=16)
    size_t off = (size_t)eid * D + (lane << 2);
    float4 pe = *(const float4*)(score + off);
    float4 sc = make_float4(pe.x + dt, pe.y + dt, pe.z + dt, pe.w + dt);
    *(float4*)(score + off) = sc;
    float4 ex = make_float4(__expf(sc.x), __expf(sc.y), __expf(sc.z), __expf(sc.w));
    float* sp = ssum + (size_t)d * D + (lane << 2);
    atomicAdd(sp + 0, ex.x); atomicAdd(sp + 1, ex.y);
    atomicAdd(sp + 2, ex.z); atomicAdd(sp + 3, ex.w);
}

__global__ void edge_agg_kernel(const float* __restrict__ V, const float* __restrict__ score,
                                const float* __restrict__ ssum, float* __restrict__ wV,
                                const int* __restrict__ src, const int* __restrict__ dst, int E)
{
    int eid  = (int)((blockIdx.x * (size_t)blockDim.x + threadIdx.x) >> 5);
    int lane = threadIdx.x & 31;
    if (eid >= E) return;
    int s = src[eid], d = dst[eid];
    size_t off = (size_t)eid * D + (lane << 2);
    float4 sc = *(const float4*)(score + off);
    float4 ss = *(const float4*)(ssum + (size_t)d * D + (lane << 2));
    float4 vv = *(const float4*)(V + (size_t)s * D + (lane << 2));
    float a0 = __expf(sc.x) / ss.x * vv.x;
    float a1 = __expf(sc.y) / ss.y * vv.y;
    float a2 = __expf(sc.z) / ss.z * vv.z;
    float a3 = __expf(sc.w) / ss.w * vv.w;
    float* wp = wV + (size_t)d * D + (lane << 2);
    atomicAdd(wp + 0, a0); atomicAdd(wp + 1, a1);
    atomicAdd(wp + 2, a2); atomicAdd(wp + 3, a3);
}

// ---------------------------------------------------------------------------
// BN finalize + apply
// ---------------------------------------------------------------------------
__global__ void bn_finalize_kernel(const double* __restrict__ stat,
                                   const float* __restrict__ gamma, const float* __restrict__ beta,
                                   float* __restrict__ osc, float* __restrict__ osh, double invM)
{
    int c = threadIdx.x;
    float mu  = (float)(stat[c] * invM);
    float var = (float)(stat[128 + c] * invM) - mu * mu;
    float rs  = rsqrtf(var + 1e-5f);
    float scv = gamma[c] * rs;
    osc[c] = scv;
    osh[c] = beta[c] - mu * scv;
}

__global__ void bn_apply_kernel(float* __restrict__ x, const float* __restrict__ sc,
                                const float* __restrict__ sh, long n4)
{
    long i = (long)blockIdx.x * blockDim.x + threadIdx.x;
    if (i >= n4) return;
    float4 v = ((float4*)x)[i];
    int c = (int)(i & 31) << 2;
    v.x = v.x * sc[c+0] + sh[c+0];
    v.y = v.y * sc[c+1] + sh[c+1];
    v.z = v.z * sc[c+2] + sh[c+2];
    v.w = v.w * sc[c+3] + sh[c+3];
    ((float4*)x)[i] = v;
}

// ---------------------------------------------------------------------------
// Launch
// ---------------------------------------------------------------------------
extern "C" void kernel_launch(void* const* d_in, const int* in_sizes, int n_in,
                              void* d_out, int out_size)
{
    const float* h    = (const float*)d_in[0];
    const float* e    = (const float*)d_in[1];
    const int*   src  = (const int*)d_in[2];
    const int*   dst  = (const int*)d_in[3];
    const float* Wq   = (const float*)d_in[4];
    const float* Wk   = (const float*)d_in[5];
    const float* Wv   = (const float*)d_in[6];
    const float* We   = (const float*)d_in[7];
    const float* Ohw  = (const float*)d_in[8];
    const float* Ohb  = (const float*)d_in[9];
    const float* Oew  = (const float*)d_in[10];
    const float* Oeb  = (const float*)d_in[11];
    const float* bn1hg = (const float*)d_in[12];
    const float* bn1hb = (const float*)d_in[13];
    const float* bn1eg = (const float*)d_in[14];
    const float* bn1eb = (const float*)d_in[15];
    const float* bn2hg = (const float*)d_in[16];
    const float* bn2hb = (const float*)d_in[17];
    const float* bn2eg = (const float*)d_in[18];
    const float* bn2eb = (const float*)d_in[19];
    const float* f1hw = (const float*)d_in[20];
    const float* f1hb = (const float*)d_in[21];
    const float* f2hw = (const float*)d_in[22];
    const float* f2hb = (const float*)d_in[23];
    const float* f1ew = (const float*)d_in[24];
    const float* f1eb = (const float*)d_in[25];
    const float* f2ew = (const float*)d_in[26];
    const float* f2eb = (const float*)d_in[27];

    const int Nn = in_sizes[0] / D;   // 50000
    const int Ne = in_sizes[2];       // 800000

    float* out   = (float*)d_out;
    float* out_h = out;
    float* out_e = out + (size_t)Nn * D;

    void* pv;
    cudaGetSymbolAddress(&pv, g_Q);     float* Q  = (float*)pv;
    cudaGetSymbolAddress(&pv, g_K);     float* Kk = (float*)pv;
    cudaGetSymbolAddress(&pv, g_V);     float* V  = (float*)pv;
    cudaGetSymbolAddress(&pv, g_ssum);  float* SS = (float*)pv;
    cudaGetSymbolAddress(&pv, g_wV);    float* WV = (float*)pv;
    cudaGetSymbolAddress(&pv, g_h1);    float* H1 = (float*)pv;
    cudaGetSymbolAddress(&pv, g_hh);    float* HH = (float*)pv;
    cudaGetSymbolAddress(&pv, g_score); float* SC = (float*)pv;
    cudaGetSymbolAddress(&pv, g_e1);    float* E1 = (float*)pv;
    cudaGetSymbolAddress(&pv, g_eh);    float* EH = (float*)pv;
    cudaGetSymbolAddress(&pv, g_stat);  double* ST = (double*)pv;
    cudaGetSymbolAddress(&pv, g_bnsc);  float* BSC = (float*)pv;
    cudaGetSymbolAddress(&pv, g_bnsh);  float* BSH = (float*)pv;

    cudaMemsetAsync(SS, 0, sizeof(float) * (size_t)Nn * D);
    cudaMemsetAsync(WV, 0, sizeof(float) * (size_t)Nn * D);
    cudaMemsetAsync(ST, 0, sizeof(double) * 4 * 2 * 128);

    dim3 blk(256);
    dim3 gN (1, (Nn + 127) / 128);
    dim3 gE (1, (Ne + 127) / 128);
    dim3 gN2(2, (Nn + 127) / 128);
    dim3 gE2(2, (Ne + 127) / 128);

    // 1) Projections (tensor core tf32)
    gemm_tc<128, 0><<<gN, blk>>>(h, Wq, 128, Q,  128, nullptr, nullptr, 0, nullptr, nullptr, nullptr, Nn);
    gemm_tc<128, 0><<<gN, blk>>>(h, Wk, 128, Kk, 128, nullptr, nullptr, 0, nullptr, nullptr, nullptr, Nn);
    gemm_tc<128, 0><<<gN, blk>>>(h, Wv, 128, V,  128, nullptr, nullptr, 0, nullptr, nullptr, nullptr, Nn);
    gemm_tc<128, 0><<<gE, blk>>>(e, We, 128, SC, 128, nullptr, nullptr, 0, nullptr, nullptr, nullptr, Ne);

    // 2) Edge attention
    int eblocks = (int)(((size_t)Ne * 32 + 255) / 256);
    edge_score_kernel<<<eblocks, 256>>>(Q, Kk, SC, SS, src, dst, Ne);
    edge_agg_kernel  <<<eblocks, 256>>>(V, SC, SS, WV, src, dst, Ne);

    // 3) Output projections + residual; BN1 stats
    gemm_tc<128, M_RESP | M_STATS><<<gN, blk>>>(WV, Ohw, 128, H1, 128, Ohb, h, 128, nullptr, nullptr, ST + 0 * 256, Nn);
    gemm_tc<128, M_RESP | M_STATS><<<gE, blk>>>(SC, Oew, 128, E1, 128, Oeb, e, 128, nullptr, nullptr, ST + 1 * 256, Ne);

    bn_finalize_kernel<<<1, 128>>>(ST + 0 * 256, bn1hg, bn1hb, BSC + 0 * 128, BSH + 0 * 128, 1.0 / Nn);
    bn_finalize_kernel<<<1, 128>>>(ST + 1 * 256, bn1eg, bn1eb, BSC + 1 * 128, BSH + 1 * 128, 1.0 / Ne);

    // 4) FFN layer 1: relu(bn1(x) @ f1 + b1), BN applied in A-load path
    gemm_tc<128, M_ABN | M_RELU><<<gN2, blk>>>(H1, f1hw, 256, HH, 256, f1hb, nullptr, 0, BSC + 0 * 128, BSH + 0 * 128, nullptr, Nn);
    gemm_tc<128, M_ABN | M_RELU><<<gE2, blk>>>(E1, f1ew, 256, EH, 256, f1eb, nullptr, 0, BSC + 1 * 128, BSH + 1 * 128, nullptr, Ne);

    // 5) FFN layer 2 + residual bn1(x); BN2 stats; write raw into out
    gemm_tc<256, M_RESBN | M_STATS><<<gN, blk>>>(HH, f2hw, 128, out_h, 128, f2hb, H1, 128, BSC + 0 * 128, BSH + 0 * 128, ST + 2 * 256, Nn);
    gemm_tc<256, M_RESBN | M_STATS><<<gE, blk>>>(EH, f2ew, 128, out_e, 128, f2eb, E1, 128, BSC + 1 * 128, BSH + 1 * 128, ST + 3 * 256, Ne);

    bn_finalize_kernel<<<1, 128>>>(ST + 2 * 256, bn2hg, bn2hb, BSC + 2 * 128, BSH + 2 * 128, 1.0 / Nn);
    bn_finalize_kernel<<<1, 128>>>(ST + 3 * 256, bn2eg, bn2eb, BSC + 3 * 128, BSH + 3 * 128, 1.0 / Ne);

    // 6) BN2 apply in-place on output
    long n4h = (long)Nn * D / 4;
    long n4e = (long)Ne * D / 4;
    bn_apply_kernel<<<(int)((n4h + 255) / 256), 256>>>(out_h, BSC + 2 * 128, BSH + 2 * 128, n4h);
    bn_apply_kernel<<<(int)((n4e + 255) / 256), 256>>>(out_e, BSC + 3 * 128, BSH + 3 * 128, n4e);
}

// round 6
// speedup vs baseline: 2.7251x; 1.1704x over previous
#include <cuda_runtime.h>
#include <cuda_fp16.h>
#include <cstdint>

// Problem constants (GraphTransformerLayer: N=50000 nodes, E=800000 edges, D=128, H=8, HD=16)
static constexpr int NNODE = 50000;
static constexpr int NEDGE = 800000;
static constexpr int D     = 128;

// ---------------------------------------------------------------------------
// Scratch (device globals; accumulators reset every launch)
// ---------------------------------------------------------------------------
__device__ float  g_Q [NNODE * D];
__device__ float  g_K [NNODE * D];
__device__ float  g_V [NNODE * D];
__device__ float  g_ssum[NNODE * D];
__device__ float  g_wV [NNODE * D];
__device__ float  g_h1 [NNODE * D];
__device__ float  g_hh [NNODE * 2 * D];
__device__ float  g_score[(size_t)NEDGE * D];
__device__ float  g_e1 [(size_t)NEDGE * D];
__device__ float  g_eh [(size_t)NEDGE * 2 * D];
__device__ double g_stat[4 * 2 * 128];
__device__ float  g_bnsc[4 * 128];
__device__ float  g_bnsh[4 * 128];
__device__ float  g_W2h[128 * 256];  // FFN1 weights with BN folded in
__device__ float  g_b2h[256];
__device__ float  g_W2e[128 * 256];
__device__ float  g_b2e[256];

enum { M_RELU = 1, M_RESP = 2, M_RESBN = 4, M_STATS = 8 };

__device__ __forceinline__ void mma_f16(float* c, const uint32_t* a, const uint32_t* b) {
    asm volatile(
        "mma.sync.aligned.m16n8k16.row.col.f32.f16.f16.f32 "
        "{%0,%1,%2,%3},{%4,%5,%6,%7},{%8,%9},{%0,%1,%2,%3};"
        : "+f"(c[0]), "+f"(c[1]), "+f"(c[2]), "+f"(c[3])
        : "r"(a[0]), "r"(a[1]), "r"(a[2]), "r"(a[3]), "r"(b[0]), "r"(b[1]));
}

// ---------------------------------------------------------------------------
// FP16 tensor-core GEMM: C[M,Nout] = A[M,KD] @ B[KD,Nout] (+bias)(+res)(+BN)(relu)(stats)
// Block tile 128x128, 128 threads (4 warps, warp tile 64x64), K-step 16,
// double-buffered smem, register prefetch. A smem [m][k2] stride 12,
// B smem transposed [n][k2] stride 12 with k-rotation swizzle (conflict-free).
// ---------------------------------------------------------------------------
template <int KD, int MODE>
__global__ __launch_bounds__(128, 2) void gemm_fp16(
    const float* __restrict__ A,
    const float* __restrict__ B, int ldb,
    float* __restrict__ C, int ldc,
    const float* __restrict__ bias,
    const float* __restrict__ resid, int ldr,
    const float* __restrict__ tsc, const float* __restrict__ tsh,
    double* __restrict__ stat,
    int M)
{
    __shared__ uint32_t As[2][128 * 12];
    __shared__ uint32_t Bs[2][128 * 12];
    __shared__ float red[2][128];

    const int tid  = threadIdx.x;
    const int lane = tid & 31;
    const int warp = tid >> 5;
    const int g    = lane >> 2;
    const int tig  = lane & 3;
    const int wm   = (warp >> 1) * 64;
    const int wn   = (warp & 1) * 64;
    const int m0   = blockIdx.y * 128;
    const int nb   = blockIdx.x * 128;
    const int rot  = (tid >> 3) & 7;   // B staging swizzle rotation (n = tid)

    float acc[4][8][4];
#pragma unroll
    for (int mt = 0; mt < 4; mt++)
#pragma unroll
        for (int nt = 0; nt < 8; nt++) {
            acc[mt][nt][0] = 0.f; acc[mt][nt][1] = 0.f;
            acc[mt][nt][2] = 0.f; acc[mt][nt][3] = 0.f;
        }

    float4 aR[4];
    float2 bR[8];

    // prologue: load tile 0
    {
#pragma unroll
        for (int i = 0; i < 4; i++) {
            int c = i * 128 + tid, m = c >> 2, kq = c & 3;
            int gm = m0 + m; gm = gm < M ? gm : (M - 1);
            aR[i] = *(const float4*)(A + (size_t)gm * KD + kq * 4);
        }
#pragma unroll
        for (int i = 0; i < 8; i++) {
            const float* p = B + (size_t)(2 * i) * ldb + nb + tid;
            bR[i] = make_float2(p[0], p[ldb]);
        }
    }

    const int nIter = KD / 16;
#pragma unroll 1
    for (int it = 0; it < nIter; ++it) {
        uint32_t* as = As[it & 1];
        uint32_t* bs = Bs[it & 1];
        // stage to smem (fp32 -> fp16)
#pragma unroll
        for (int i = 0; i < 4; i++) {
            int c = i * 128 + tid, m = c >> 2, kq = c & 3;
            __half2 h0 = __floats2half2_rn(aR[i].x, aR[i].y);
            __half2 h1 = __floats2half2_rn(aR[i].z, aR[i].w);
            *(uint2*)&as[m * 12 + kq * 2] =
                make_uint2(*(uint32_t*)&h0, *(uint32_t*)&h1);
        }
#pragma unroll
        for (int i = 0; i < 8; i++) {
            __half2 hb = __floats2half2_rn(bR[i].x, bR[i].y);
            bs[tid * 12 + ((i + rot) & 7)] = *(uint32_t*)&hb;
        }
        __syncthreads();

        // prefetch next tile into registers (overlaps with MMA below)
        if (it + 1 < nIter) {
            int k0 = (it + 1) * 16;
#pragma unroll
            for (int i = 0; i < 4; i++) {
                int c = i * 128 + tid, m = c >> 2, kq = c & 3;
                int gm = m0 + m; gm = gm < M ? gm : (M - 1);
                aR[i] = *(const float4*)(A + (size_t)gm * KD + k0 + kq * 4);
            }
#pragma unroll
            for (int i = 0; i < 8; i++) {
                const float* p = B + (size_t)(k0 + 2 * i) * ldb + nb + tid;
                bR[i] = make_float2(p[0], p[ldb]);
            }
        }

        // fragments + 32 MMAs (one k16 chunk)
        uint32_t af[4][4], bf[8][2];
#pragma unroll
        for (int mt = 0; mt < 4; mt++) {
            int r = wm + mt * 16 + g;
            af[mt][0] = as[r * 12 + tig];
            af[mt][1] = as[(r + 8) * 12 + tig];
            af[mt][2] = as[r * 12 + tig + 4];
            af[mt][3] = as[(r + 8) * 12 + tig + 4];
        }
#pragma unroll
        for (int nt = 0; nt < 8; nt++) {
            int cn = wn + nt * 8 + g;
            bf[nt][0] = bs[cn * 12 + ((tig + nt) & 7)];
            bf[nt][1] = bs[cn * 12 + ((tig + 4 + nt) & 7)];
        }
#pragma unroll
        for (int mt = 0; mt < 4; mt++)
#pragma unroll
            for (int nt = 0; nt < 8; nt++)
                mma_f16(acc[mt][nt], af[mt], bf[nt]);
    }

    // ---------------- Epilogue ----------------
    const int cb = wn + (tig << 1);
    float s[8][2], q[8][2];
#pragma unroll
    for (int nt = 0; nt < 8; nt++) { s[nt][0]=0.f; s[nt][1]=0.f; q[nt][0]=0.f; q[nt][1]=0.f; }

#pragma unroll
    for (int mt = 0; mt < 4; mt++) {
        int r0 = m0 + wm + mt * 16 + g;
#pragma unroll
        for (int half = 0; half < 2; half++) {
            int gm = r0 + half * 8;
            if (gm >= M) continue;
#pragma unroll
            for (int nt = 0; nt < 8; nt++) {
                int c = nb + cb + nt * 8;
                float x0 = acc[mt][nt][half * 2 + 0];
                float x1 = acc[mt][nt][half * 2 + 1];
                if (bias) { x0 += bias[c]; x1 += bias[c + 1]; }
                if (MODE & M_RESP) {
                    float2 rr = *(const float2*)(resid + (size_t)gm * ldr + c);
                    x0 += rr.x; x1 += rr.y;
                }
                if (MODE & M_RESBN) {
                    float2 rr = *(const float2*)(resid + (size_t)gm * ldr + c);
                    x0 += rr.x * tsc[c] + tsh[c];
                    x1 += rr.y * tsc[c + 1] + tsh[c + 1];
                }
                if (MODE & M_RELU) { x0 = fmaxf(x0, 0.f); x1 = fmaxf(x1, 0.f); }
                *(float2*)(C + (size_t)gm * ldc + c) = make_float2(x0, x1);
                if (MODE & M_STATS) {
                    s[nt][0] += x0; s[nt][1] += x1;
                    q[nt][0] += x0 * x0; q[nt][1] += x1 * x1;
                }
            }
        }
    }

    if (MODE & M_STATS) {
        __syncthreads();
        red[0][tid] = 0.f; red[1][tid] = 0.f;
        __syncthreads();
#pragma unroll
        for (int nt = 0; nt < 8; nt++) {
            int c = cb + nt * 8;   // STATS modes have Nout=128, nb=0
            atomicAdd(&red[0][c],     s[nt][0]);
            atomicAdd(&red[0][c + 1], s[nt][1]);
            atomicAdd(&red[1][c],     q[nt][0]);
            atomicAdd(&red[1][c + 1], q[nt][1]);
        }
        __syncthreads();
        atomicAdd(&stat[tid],       (double)red[0][tid]);
        atomicAdd(&stat[128 + tid], (double)red[1][tid]);
    }
}

// ---------------------------------------------------------------------------
// FFN1 prep: fold BN1 (per-input-column affine) into W1 and bias.
// (x*sc+sh) @ W = x @ (diag(sc) W) + sh^T W
// ---------------------------------------------------------------------------
__global__ void ffn1_prep(const float* __restrict__ W, const float* __restrict__ bias,
                          const float* __restrict__ sc, const float* __restrict__ sh,
                          float* __restrict__ W2, float* __restrict__ b2)
{
    int n = threadIdx.x;   // 256 threads, one per output column
    float a = bias[n];
    for (int k = 0; k < 128; k++) {
        float b = W[k * 256 + n];
        W2[k * 256 + n] = sc[k] * b;
        a += sh[k] * b;
    }
    b2[n] = a;
}

// ---------------------------------------------------------------------------
// Edge kernels: one warp per edge; lane handles channels [4*lane, 4*lane+4)
// Softmax without max-shift (scores bounded, shift-invariant).
// ---------------------------------------------------------------------------
__global__ void edge_score_kernel(const float* __restrict__ Q, const float* __restrict__ K,
                                  float* __restrict__ score, float* __restrict__ ssum,
                                  const int* __restrict__ src, const int* __restrict__ dst, int E)
{
    int eid  = (int)((blockIdx.x * (size_t)blockDim.x + threadIdx.x) >> 5);
    int lane = threadIdx.x & 31;
    if (eid >= E) return;
    int s = src[eid], d = dst[eid];
    float4 kk = *(const float4*)(K + (size_t)s * D + (lane << 2));
    float4 qq = *(const float4*)(Q + (size_t)d * D + (lane << 2));
    float p = kk.x*qq.x + kk.y*qq.y + kk.z*qq.z + kk.w*qq.w;
    p += __shfl_xor_sync(0xffffffffu, p, 1);
    p += __shfl_xor_sync(0xffffffffu, p, 2);   // dot over 16 channels of this head
    float dt = p * 0.25f;                      // / sqrt(HD=16)
    size_t off = (size_t)eid * D + (lane << 2);
    float4 pe = *(const float4*)(score + off);
    float4 sc = make_float4(pe.x + dt, pe.y + dt, pe.z + dt, pe.w + dt);
    *(float4*)(score + off) = sc;
    float4 ex = make_float4(__expf(sc.x), __expf(sc.y), __expf(sc.z), __expf(sc.w));
    float* sp = ssum + (size_t)d * D + (lane << 2);
    atomicAdd(sp + 0, ex.x); atomicAdd(sp + 1, ex.y);
    atomicAdd(sp + 2, ex.z); atomicAdd(sp + 3, ex.w);
}

__global__ void edge_agg_kernel(const float* __restrict__ V, const float* __restrict__ score,
                                const float* __restrict__ ssum, float* __restrict__ wV,
                                const int* __restrict__ src, const int* __restrict__ dst, int E)
{
    int eid  = (int)((blockIdx.x * (size_t)blockDim.x + threadIdx.x) >> 5);
    int lane = threadIdx.x & 31;
    if (eid >= E) return;
    int s = src[eid], d = dst[eid];
    size_t off = (size_t)eid * D + (lane << 2);
    float4 sc = *(const float4*)(score + off);
    float4 ss = *(const float4*)(ssum + (size_t)d * D + (lane << 2));
    float4 vv = *(const float4*)(V + (size_t)s * D + (lane << 2));
    float a0 = __expf(sc.x) / ss.x * vv.x;
    float a1 = __expf(sc.y) / ss.y * vv.y;
    float a2 = __expf(sc.z) / ss.z * vv.z;
    float a3 = __expf(sc.w) / ss.w * vv.w;
    float* wp = wV + (size_t)d * D + (lane << 2);
    atomicAdd(wp + 0, a0); atomicAdd(wp + 1, a1);
    atomicAdd(wp + 2, a2); atomicAdd(wp + 3, a3);
}

// ---------------------------------------------------------------------------
// BN finalize + apply
// ---------------------------------------------------------------------------
__global__ void bn_finalize_kernel(const double* __restrict__ stat,
                                   const float* __restrict__ gamma, const float* __restrict__ beta,
                                   float* __restrict__ osc, float* __restrict__ osh, double invM)
{
    int c = threadIdx.x;
    float mu  = (float)(stat[c] * invM);
    float var = (float)(stat[128 + c] * invM) - mu * mu;
    float rs  = rsqrtf(var + 1e-5f);
    float scv = gamma[c] * rs;
    osc[c] = scv;
    osh[c] = beta[c] - mu * scv;
}

__global__ void bn_apply_kernel(float* __restrict__ x, const float* __restrict__ sc,
                                const float* __restrict__ sh, long n4)
{
    long i = (long)blockIdx.x * blockDim.x + threadIdx.x;
    if (i >= n4) return;
    float4 v = ((float4*)x)[i];
    int c = (int)(i & 31) << 2;
    v.x = v.x * sc[c+0] + sh[c+0];
    v.y = v.y * sc[c+1] + sh[c+1];
    v.z = v.z * sc[c+2] + sh[c+2];
    v.w = v.w * sc[c+3] + sh[c+3];
    ((float4*)x)[i] = v;
}

// ---------------------------------------------------------------------------
// Launch
// ---------------------------------------------------------------------------
extern "C" void kernel_launch(void* const* d_in, const int* in_sizes, int n_in,
                              void* d_out, int out_size)
{
    const float* h    = (const float*)d_in[0];
    const float* e    = (const float*)d_in[1];
    const int*   src  = (const int*)d_in[2];
    const int*   dst  = (const int*)d_in[3];
    const float* Wq   = (const float*)d_in[4];
    const float* Wk   = (const float*)d_in[5];
    const float* Wv   = (const float*)d_in[6];
    const float* We   = (const float*)d_in[7];
    const float* Ohw  = (const float*)d_in[8];
    const float* Ohb  = (const float*)d_in[9];
    const float* Oew  = (const float*)d_in[10];
    const float* Oeb  = (const float*)d_in[11];
    const float* bn1hg = (const float*)d_in[12];
    const float* bn1hb = (const float*)d_in[13];
    const float* bn1eg = (const float*)d_in[14];
    const float* bn1eb = (const float*)d_in[15];
    const float* bn2hg = (const float*)d_in[16];
    const float* bn2hb = (const float*)d_in[17];
    const float* bn2eg = (const float*)d_in[18];
    const float* bn2eb = (const float*)d_in[19];
    const float* f1hw = (const float*)d_in[20];
    const float* f1hb = (const float*)d_in[21];
    const float* f2hw = (const float*)d_in[22];
    const float* f2hb = (const float*)d_in[23];
    const float* f1ew = (const float*)d_in[24];
    const float* f1eb = (const float*)d_in[25];
    const float* f2ew = (const float*)d_in[26];
    const float* f2eb = (const float*)d_in[27];

    const int Nn = in_sizes[0] / D;   // 50000
    const int Ne = in_sizes[2];       // 800000

    float* out   = (float*)d_out;
    float* out_h = out;
    float* out_e = out + (size_t)Nn * D;

    void* pv;
    cudaGetSymbolAddress(&pv, g_Q);     float* Q  = (float*)pv;
    cudaGetSymbolAddress(&pv, g_K);     float* Kk = (float*)pv;
    cudaGetSymbolAddress(&pv, g_V);     float* V  = (float*)pv;
    cudaGetSymbolAddress(&pv, g_ssum);  float* SS = (float*)pv;
    cudaGetSymbolAddress(&pv, g_wV);    float* WV = (float*)pv;
    cudaGetSymbolAddress(&pv, g_h1);    float* H1 = (float*)pv;
    cudaGetSymbolAddress(&pv, g_hh);    float* HH = (float*)pv;
    cudaGetSymbolAddress(&pv, g_score); float* SC = (float*)pv;
    cudaGetSymbolAddress(&pv, g_e1);    float* E1 = (float*)pv;
    cudaGetSymbolAddress(&pv, g_eh);    float* EH = (float*)pv;
    cudaGetSymbolAddress(&pv, g_stat);  double* ST = (double*)pv;
    cudaGetSymbolAddress(&pv, g_bnsc);  float* BSC = (float*)pv;
    cudaGetSymbolAddress(&pv, g_bnsh);  float* BSH = (float*)pv;
    cudaGetSymbolAddress(&pv, g_W2h);   float* W2h = (float*)pv;
    cudaGetSymbolAddress(&pv, g_b2h);   float* b2h = (float*)pv;
    cudaGetSymbolAddress(&pv, g_W2e);   float* W2e = (float*)pv;
    cudaGetSymbolAddress(&pv, g_b2e);   float* b2e = (float*)pv;

    cudaMemsetAsync(SS, 0, sizeof(float) * (size_t)Nn * D);
    cudaMemsetAsync(WV, 0, sizeof(float) * (size_t)Nn * D);
    cudaMemsetAsync(ST, 0, sizeof(double) * 4 * 2 * 128);

    dim3 blk(128);
    dim3 gN (1, (Nn + 127) / 128);
    dim3 gE (1, (Ne + 127) / 128);
    dim3 gN2(2, (Nn + 127) / 128);
    dim3 gE2(2, (Ne + 127) / 128);

    // 1) Projections (fp16 tensor core)
    gemm_fp16<128, 0><<<gN, blk>>>(h, Wq, 128, Q,  128, nullptr, nullptr, 0, nullptr, nullptr, nullptr, Nn);
    gemm_fp16<128, 0><<<gN, blk>>>(h, Wk, 128, Kk, 128, nullptr, nullptr, 0, nullptr, nullptr, nullptr, Nn);
    gemm_fp16<128, 0><<<gN, blk>>>(h, Wv, 128, V,  128, nullptr, nullptr, 0, nullptr, nullptr, nullptr, Nn);
    gemm_fp16<128, 0><<<gE, blk>>>(e, We, 128, SC, 128, nullptr, nullptr, 0, nullptr, nullptr, nullptr, Ne);

    // 2) Edge attention
    int eblocks = (int)(((size_t)Ne * 32 + 255) / 256);
    edge_score_kernel<<<eblocks, 256>>>(Q, Kk, SC, SS, src, dst, Ne);
    edge_agg_kernel  <<<eblocks, 256>>>(V, SC, SS, WV, src, dst, Ne);

    // 3) Output projections + residual; BN1 stats
    gemm_fp16<128, M_RESP | M_STATS><<<gN, blk>>>(WV, Ohw, 128, H1, 128, Ohb, h, 128, nullptr, nullptr, ST + 0 * 256, Nn);
    gemm_fp16<128, M_RESP | M_STATS><<<gE, blk>>>(SC, Oew, 128, E1, 128, Oeb, e, 128, nullptr, nullptr, ST + 1 * 256, Ne);

    bn_finalize_kernel<<<1, 128>>>(ST + 0 * 256, bn1hg, bn1hb, BSC + 0 * 128, BSH + 0 * 128, 1.0 / Nn);
    bn_finalize_kernel<<<1, 128>>>(ST + 1 * 256, bn1eg, bn1eb, BSC + 1 * 128, BSH + 1 * 128, 1.0 / Ne);

    // 3b) Fold BN1 into FFN1 weights/bias
    ffn1_prep<<<1, 256>>>(f1hw, f1hb, BSC + 0 * 128, BSH + 0 * 128, W2h, b2h);
    ffn1_prep<<<1, 256>>>(f1ew, f1eb, BSC + 1 * 128, BSH + 1 * 128, W2e, b2e);

    // 4) FFN layer 1: relu(x @ W2 + b2)   (BN folded into W2/b2)
    gemm_fp16<128, M_RELU><<<gN2, blk>>>(H1, W2h, 256, HH, 256, b2h, nullptr, 0, nullptr, nullptr, nullptr, Nn);
    gemm_fp16<128, M_RELU><<<gE2, blk>>>(E1, W2e, 256, EH, 256, b2e, nullptr, 0, nullptr, nullptr, nullptr, Ne);

    // 5) FFN layer 2 + residual bn1(x); BN2 stats; write raw into out
    gemm_fp16<256, M_RESBN | M_STATS><<<gN, blk>>>(HH, f2hw, 128, out_h, 128, f2hb, H1, 128, BSC + 0 * 128, BSH + 0 * 128, ST + 2 * 256, Nn);
    gemm_fp16<256, M_RESBN | M_STATS><<<gE, blk>>>(EH, f2ew, 128, out_e, 128, f2eb, E1, 128, BSC + 1 * 128, BSH + 1 * 128, ST + 3 * 256, Ne);

    bn_finalize_kernel<<<1, 128>>>(ST + 2 * 256, bn2hg, bn2hb, BSC + 2 * 128, BSH + 2 * 128, 1.0 / Nn);
    bn_finalize_kernel<<<1, 128>>>(ST + 3 * 256, bn2eg, bn2eb, BSC + 3 * 128, BSH + 3 * 128, 1.0 / Ne);

    // 6) BN2 apply in-place on output
    long n4h = (long)Nn * D / 4;
    long n4e = (long)Ne * D / 4;
    bn_apply_kernel<<<(int)((n4h + 255) / 256), 256>>>(out_h, BSC + 2 * 128, BSH + 2 * 128, n4h);
    bn_apply_kernel<<<(int)((n4e + 255) / 256), 256>>>(out_e, BSC + 3 * 128, BSH + 3 * 128, n4e);
}

// round 9
// speedup vs baseline: 2.8660x; 1.0517x over previous
#include <cuda_runtime.h>
#include <cuda_fp16.h>
#include <cstdint>

// Problem constants (GraphTransformerLayer: N=50000 nodes, E=800000 edges, D=128, H=8, HD=16)
static constexpr int NNODE = 50000;
static constexpr int NEDGE = 800000;
static constexpr int D     = 128;

// ---------------------------------------------------------------------------
// Scratch (device globals)
// ---------------------------------------------------------------------------
__device__ __half g_Q [NNODE * D];                 // Q proj; later reused as h raw pre-BN2
__device__ __half g_K [NNODE * D];
__device__ __half g_V [NNODE * D];
__device__ float  g_ssum[NNODE * D];
__device__ float  g_wV [NNODE * D];
__device__ __half g_h1 [NNODE * D];
__device__ __half g_hh [NNODE * 2 * D];
__device__ __half g_score[(size_t)NEDGE * D];      // pe->score; later reused as e raw pre-BN2
__device__ __half g_e1 [(size_t)NEDGE * D];
__device__ __half g_eh [(size_t)NEDGE * 2 * D];
__device__ double g_stat[4 * 2 * 128];
__device__ float  g_bnsc[4 * 128];
__device__ float  g_bnsh[4 * 128];
// fp16 transposed weights Bt[n][k]
__device__ __half g_Bq [128 * 128];
__device__ __half g_Bk [128 * 128];
__device__ __half g_Bv [128 * 128];
__device__ __half g_Be [128 * 128];
__device__ __half g_BOh[128 * 128];
__device__ __half g_BOe[128 * 128];
__device__ __half g_W1th[256 * 128];   // FFN1 (BN folded) transposed
__device__ __half g_W1te[256 * 128];
__device__ float  g_b2h[256];
__device__ float  g_b2e[256];
__device__ __half g_Bf2h[128 * 256];
__device__ __half g_Bf2e[128 * 256];

enum { M_RELU = 1, M_RESP = 2, M_RESBN = 4, M_STATS = 8 };

__device__ __forceinline__ void mma_f16(float* c, const uint32_t* a, const uint32_t* b) {
    asm volatile(
        "mma.sync.aligned.m16n8k16.row.col.f32.f16.f16.f32 "
        "{%0,%1,%2,%3},{%4,%5,%6,%7},{%8,%9},{%0,%1,%2,%3};"
        : "+f"(c[0]), "+f"(c[1]), "+f"(c[2]), "+f"(c[3])
        : "r"(a[0]), "r"(a[1]), "r"(a[2]), "r"(a[3]), "r"(b[0]), "r"(b[1]));
}

__device__ __forceinline__ void cp_async16(uint32_t smem, const void* gptr) {
    asm volatile("cp.async.cg.shared.global [%0], [%1], 16;" :: "r"(smem), "l"(gptr));
}
__device__ __forceinline__ void cp_commit() { asm volatile("cp.async.commit_group;"); }
__device__ __forceinline__ void cp_wait0()  { asm volatile("cp.async.wait_group 0;"); }

// ---------------------------------------------------------------------------
// FP16 tensor-core GEMM: C = A[M,KD] @ Bt^T (+bias)(+res)(+BN-res)(relu)(stats)
// Bt is fp16 [Nout][KD] (k-contiguous). Block 128x128, 128 thr, warp 64x64.
// Double-buffered; B (and A when fp16) staged via cp.async.
// smem layout [row][k2] stride 12 words: fragment LDS bank-conflict-free.
// ---------------------------------------------------------------------------
template <int KD, int MODE, bool AH, bool RH>
__global__ __launch_bounds__(128, 2) void gemm2(
    const void* __restrict__ Av, const __half* __restrict__ Bt,
    __half* __restrict__ C, int ldc,
    const float* __restrict__ bias,
    const void* __restrict__ residv, int ldr,
    const float* __restrict__ tsc, const float* __restrict__ tsh,
    double* __restrict__ stat, int M)
{
    __shared__ uint32_t As[2][128 * 12];
    __shared__ uint32_t Bs[2][128 * 12];
    __shared__ float red[2][128];

    const int tid  = threadIdx.x;
    const int lane = tid & 31;
    const int warp = tid >> 5;
    const int g    = lane >> 2;
    const int tig  = lane & 3;
    const int wm   = (warp >> 1) * 64;
    const int wn   = (warp & 1) * 64;
    const int m0   = blockIdx.y * 128;
    const int nb   = blockIdx.x * 128;

    const float*  Af = (const float*)Av;
    const __half* Ah = (const __half*)Av;

    uint32_t sA[2], sB[2];
    sA[0] = (uint32_t)__cvta_generic_to_shared(&As[0][0]);
    sA[1] = (uint32_t)__cvta_generic_to_shared(&As[1][0]);
    sB[0] = (uint32_t)__cvta_generic_to_shared(&Bs[0][0]);
    sB[1] = (uint32_t)__cvta_generic_to_shared(&Bs[1][0]);

    float acc[4][8][4];
#pragma unroll
    for (int mt = 0; mt < 4; mt++)
#pragma unroll
        for (int nt = 0; nt < 8; nt++) {
            acc[mt][nt][0] = 0.f; acc[mt][nt][1] = 0.f;
            acc[mt][nt][2] = 0.f; acc[mt][nt][3] = 0.f;
        }

    // B row pointer for this thread (n = nb + tid)
    const __half* brow = Bt + (size_t)(nb + tid) * KD;
    // A row (fp16 path)
    int gmr = m0 + tid; if (gmr >= M) gmr = M - 1;
    const __half* arow = Ah + (size_t)gmr * KD;

    float4 aR[4];

    auto stageB = [&](int it, int buf) {
        int k0 = it * 16;
        uint32_t d0 = sB[buf] + (uint32_t)(tid * 12) * 4;
        cp_async16(d0,      brow + k0);
        cp_async16(d0 + 16, brow + k0 + 8);
    };
    auto stageAh = [&](int it, int buf) {
        int k0 = it * 16;
        uint32_t d0 = sA[buf] + (uint32_t)(tid * 12) * 4;
        cp_async16(d0,      arow + k0);
        cp_async16(d0 + 16, arow + k0 + 8);
    };
    auto ldgA = [&](int it) {
        int k0 = it * 16;
#pragma unroll
        for (int i = 0; i < 4; i++) {
            int c = i * 128 + tid, m = c >> 2, kq = c & 3;
            int gm = m0 + m; gm = gm < M ? gm : (M - 1);
            aR[i] = *(const float4*)(Af + (size_t)gm * KD + k0 + kq * 4);
        }
    };
    auto stsA = [&](int buf) {
        uint32_t* as = As[buf];
#pragma unroll
        for (int i = 0; i < 4; i++) {
            int c = i * 128 + tid, m = c >> 2, kq = c & 3;
            __half2 h0 = __floats2half2_rn(aR[i].x, aR[i].y);
            __half2 h1 = __floats2half2_rn(aR[i].z, aR[i].w);
            *(uint2*)&as[m * 12 + kq * 2] = make_uint2(*(uint32_t*)&h0, *(uint32_t*)&h1);
        }
    };

    // prologue
    stageB(0, 0);
    if (AH) stageAh(0, 0);
    cp_commit();
    if (!AH) ldgA(0);

    const int nIter = KD / 16;
#pragma unroll 1
    for (int it = 0; it < nIter; ++it) {
        int buf = it & 1;
        if (!AH) stsA(buf);
        cp_wait0();
        __syncthreads();
        if (it + 1 < nIter) {
            stageB(it + 1, buf ^ 1);
            if (AH) stageAh(it + 1, buf ^ 1);
            cp_commit();
            if (!AH) ldgA(it + 1);
        }
        const uint32_t* as = As[buf];
        const uint32_t* bs = Bs[buf];
        uint32_t af[4][4], bf[8][2];
#pragma unroll
        for (int mt = 0; mt < 4; mt++) {
            int r = wm + mt * 16 + g;
            af[mt][0] = as[r * 12 + tig];
            af[mt][1] = as[(r + 8) * 12 + tig];
            af[mt][2] = as[r * 12 + tig + 4];
            af[mt][3] = as[(r + 8) * 12 + tig + 4];
        }
#pragma unroll
        for (int nt = 0; nt < 8; nt++) {
            int cn = wn + nt * 8 + g;
            bf[nt][0] = bs[cn * 12 + tig];
            bf[nt][1] = bs[cn * 12 + tig + 4];
        }
#pragma unroll
        for (int mt = 0; mt < 4; mt++)
#pragma unroll
            for (int nt = 0; nt < 8; nt++)
                mma_f16(acc[mt][nt], af[mt], bf[nt]);
    }

    // ---------------- Epilogue ----------------
    const int cb = wn + (tig << 1);
    float s[8][2], q[8][2];
#pragma unroll
    for (int nt = 0; nt < 8; nt++) { s[nt][0]=0.f; s[nt][1]=0.f; q[nt][0]=0.f; q[nt][1]=0.f; }

#pragma unroll
    for (int mt = 0; mt < 4; mt++) {
        int r0 = m0 + wm + mt * 16 + g;
#pragma unroll
        for (int half = 0; half < 2; half++) {
            int gm = r0 + half * 8;
            if (gm >= M) continue;
#pragma unroll
            for (int nt = 0; nt < 8; nt++) {
                int c = nb + cb + nt * 8;
                float x0 = acc[mt][nt][half * 2 + 0];
                float x1 = acc[mt][nt][half * 2 + 1];
                if (bias) { x0 += bias[c]; x1 += bias[c + 1]; }
                if (MODE & (M_RESP | M_RESBN)) {
                    float2 rr;
                    if (RH) rr = __half22float2(*(const __half2*)((const __half*)residv + (size_t)gm * ldr + c));
                    else    rr = *(const float2*)((const float*)residv + (size_t)gm * ldr + c);
                    if (MODE & M_RESP) { x0 += rr.x; x1 += rr.y; }
                    else {
                        x0 += rr.x * tsc[c] + tsh[c];
                        x1 += rr.y * tsc[c + 1] + tsh[c + 1];
                    }
                }
                if (MODE & M_RELU) { x0 = fmaxf(x0, 0.f); x1 = fmaxf(x1, 0.f); }
                *(__half2*)(C + (size_t)gm * ldc + c) = __floats2half2_rn(x0, x1);
                if (MODE & M_STATS) {
                    s[nt][0] += x0; s[nt][1] += x1;
                    q[nt][0] += x0 * x0; q[nt][1] += x1 * x1;
                }
            }
        }
    }

    if (MODE & M_STATS) {
        __syncthreads();
        red[0][tid] = 0.f; red[1][tid] = 0.f;
        __syncthreads();
#pragma unroll
        for (int nt = 0; nt < 8; nt++) {
            int c = cb + nt * 8;   // STATS modes have Nout=128, nb=0
            atomicAdd(&red[0][c],     s[nt][0]);
            atomicAdd(&red[0][c + 1], s[nt][1]);
            atomicAdd(&red[1][c],     q[nt][0]);
            atomicAdd(&red[1][c + 1], q[nt][1]);
        }
        __syncthreads();
        atomicAdd(&stat[tid],       (double)red[0][tid]);
        atomicAdd(&stat[128 + tid], (double)red[1][tid]);
    }
}

// ---------------------------------------------------------------------------
// Weight prep: fp32 W[K][N] -> fp16 Bt[N][K]
// ---------------------------------------------------------------------------
__global__ void wtrans(const float* __restrict__ W, __half* __restrict__ Bt, int K, int N)
{
    int idx = blockIdx.x * 256 + threadIdx.x;
    if (idx >= K * N) return;
    int n = idx % N, k = idx / N;
    Bt[(size_t)n * K + k] = __float2half(W[idx]);
}

// FFN1 prep: fold BN1 into W1 (transposed fp16) and bias.
__global__ void ffn1_prep_t(const float* __restrict__ W, const float* __restrict__ bias,
                            const float* __restrict__ sc, const float* __restrict__ sh,
                            __half* __restrict__ Wt, float* __restrict__ b2)
{
    int n = threadIdx.x;   // 256 threads
    float a = bias[n];
    for (int k = 0; k < 128; k++) {
        float w = W[k * 256 + n];
        Wt[n * 128 + k] = __float2half(sc[k] * w);
        a += sh[k] * w;
    }
    b2[n] = a;
}

// ---------------------------------------------------------------------------
// Edge kernels (fp16 Q/K/V/score, fp32 accumulators)
// ---------------------------------------------------------------------------
__global__ void edge_score_kernel(const __half* __restrict__ Q, const __half* __restrict__ K,
                                  __half* __restrict__ score, float* __restrict__ ssum,
                                  const int* __restrict__ src, const int* __restrict__ dst, int E)
{
    int eid  = (int)((blockIdx.x * (size_t)blockDim.x + threadIdx.x) >> 5);
    int lane = threadIdx.x & 31;
    if (eid >= E) return;
    int s = src[eid], d = dst[eid];
    uint2 kr = *(const uint2*)(K + (size_t)s * D + (lane << 2));
    uint2 qr = *(const uint2*)(Q + (size_t)d * D + (lane << 2));
    float2 k0 = __half22float2(*(__half2*)&kr.x), k1 = __half22float2(*(__half2*)&kr.y);
    float2 q0 = __half22float2(*(__half2*)&qr.x), q1 = __half22float2(*(__half2*)&qr.y);
    float p = k0.x*q0.x + k0.y*q0.y + k1.x*q1.x + k1.y*q1.y;
    p += __shfl_xor_sync(0xffffffffu, p, 1);
    p += __shfl_xor_sync(0xffffffffu, p, 2);   // dot over 16 channels of this head
    float dt = p * 0.25f;                      // / sqrt(HD=16)
    size_t off = (size_t)eid * D + (lane << 2);
    uint2 pr = *(const uint2*)(score + off);
    float2 p0 = __half22float2(*(__half2*)&pr.x), p1 = __half22float2(*(__half2*)&pr.y);
    __half2 h0 = __floats2half2_rn(p0.x + dt, p0.y + dt);
    __half2 h1 = __floats2half2_rn(p1.x + dt, p1.y + dt);
    *(uint2*)(score + off) = make_uint2(*(uint32_t*)&h0, *(uint32_t*)&h1);
    // exp of the ROUNDED score -> consistent with agg pass
    float2 f0 = __half22float2(h0), f1 = __half22float2(h1);
    float* sp = ssum + (size_t)d * D + (lane << 2);
    atomicAdd(sp + 0, __expf(f0.x)); atomicAdd(sp + 1, __expf(f0.y));
    atomicAdd(sp + 2, __expf(f1.x)); atomicAdd(sp + 3, __expf(f1.y));
}

__global__ void edge_agg_kernel(const __half* __restrict__ V, const __half* __restrict__ score,
                                const float* __restrict__ ssum, float* __restrict__ wV,
                                const int* __restrict__ src, const int* __restrict__ dst, int E)
{
    int eid  = (int)((blockIdx.x * (size_t)blockDim.x + threadIdx.x) >> 5);
    int lane = threadIdx.x & 31;
    if (eid >= E) return;
    int s = src[eid], d = dst[eid];
    size_t off = (size_t)eid * D + (lane << 2);
    uint2 sr = *(const uint2*)(score + off);
    float2 s0 = __half22float2(*(__half2*)&sr.x), s1 = __half22float2(*(__half2*)&sr.y);
    float4 ss = *(const float4*)(ssum + (size_t)d * D + (lane << 2));
    uint2 vr = *(const uint2*)(V + (size_t)s * D + (lane << 2));
    float2 v0 = __half22float2(*(__half2*)&vr.x), v1 = __half22float2(*(__half2*)&vr.y);
    float* wp = wV + (size_t)d * D + (lane << 2);
    atomicAdd(wp + 0, __expf(s0.x) / ss.x * v0.x);
    atomicAdd(wp + 1, __expf(s0.y) / ss.y * v0.y);
    atomicAdd(wp + 2, __expf(s1.x) / ss.z * v1.x);
    atomicAdd(wp + 3, __expf(s1.y) / ss.w * v1.y);
}

// ---------------------------------------------------------------------------
// BN finalize + apply (half raw -> fp32 out)
// ---------------------------------------------------------------------------
__global__ void bn_finalize_kernel(const double* __restrict__ stat,
                                   const float* __restrict__ gamma, const float* __restrict__ beta,
                                   float* __restrict__ osc, float* __restrict__ osh, double invM)
{
    int c = threadIdx.x;
    float mu  = (float)(stat[c] * invM);
    float var = (float)(stat[128 + c] * invM) - mu * mu;
    float rs  = rsqrtf(var + 1e-5f);
    float scv = gamma[c] * rs;
    osc[c] = scv;
    osh[c] = beta[c] - mu * scv;
}

__global__ void bn_apply_h2f(const __half* __restrict__ raw, float* __restrict__ out,
                             const float* __restrict__ sc, const float* __restrict__ sh, long n4)
{
    long i = (long)blockIdx.x * blockDim.x + threadIdx.x;
    if (i >= n4) return;
    uint2 r = ((const uint2*)raw)[i];
    float2 a = __half22float2(*(__half2*)&r.x);
    float2 b = __half22float2(*(__half2*)&r.y);
    int c = (int)(i & 31) << 2;
    float4 v;
    v.x = a.x * sc[c+0] + sh[c+0];
    v.y = a.y * sc[c+1] + sh[c+1];
    v.z = b.x * sc[c+2] + sh[c+2];
    v.w = b.y * sc[c+3] + sh[c+3];
    ((float4*)out)[i] = v;
}

// ---------------------------------------------------------------------------
// Launch
// ---------------------------------------------------------------------------
extern "C" void kernel_launch(void* const* d_in, const int* in_sizes, int n_in,
                              void* d_out, int out_size)
{
    const float* h    = (const float*)d_in[0];
    const float* e    = (const float*)d_in[1];
    const int*   src  = (const int*)d_in[2];
    const int*   dst  = (const int*)d_in[3];
    const float* Wq   = (const float*)d_in[4];
    const float* Wk   = (const float*)d_in[5];
    const float* Wv   = (const float*)d_in[6];
    const float* We   = (const float*)d_in[7];
    const float* Ohw  = (const float*)d_in[8];
    const float* Ohb  = (const float*)d_in[9];
    const float* Oew  = (const float*)d_in[10];
    const float* Oeb  = (const float*)d_in[11];
    const float* bn1hg = (const float*)d_in[12];
    const float* bn1hb = (const float*)d_in[13];
    const float* bn1eg = (const float*)d_in[14];
    const float* bn1eb = (const float*)d_in[15];
    const float* bn2hg = (const float*)d_in[16];
    const float* bn2hb = (const float*)d_in[17];
    const float* bn2eg = (const float*)d_in[18];
    const float* bn2eb = (const float*)d_in[19];
    const float* f1hw = (const float*)d_in[20];
    const float* f1hb = (const float*)d_in[21];
    const float* f2hw = (const float*)d_in[22];
    const float* f2hb = (const float*)d_in[23];
    const float* f1ew = (const float*)d_in[24];
    const float* f1eb = (const float*)d_in[25];
    const float* f2ew = (const float*)d_in[26];
    const float* f2eb = (const float*)d_in[27];

    const int Nn = in_sizes[0] / D;   // 50000
    const int Ne = in_sizes[2];       // 800000

    float* out   = (float*)d_out;
    float* out_h = out;
    float* out_e = out + (size_t)Nn * D;

    void* pv;
    cudaGetSymbolAddress(&pv, g_Q);     __half* Q  = (__half*)pv;
    cudaGetSymbolAddress(&pv, g_K);     __half* Kk = (__half*)pv;
    cudaGetSymbolAddress(&pv, g_V);     __half* V  = (__half*)pv;
    cudaGetSymbolAddress(&pv, g_ssum);  float*  SS = (float*)pv;
    cudaGetSymbolAddress(&pv, g_wV);    float*  WV = (float*)pv;
    cudaGetSymbolAddress(&pv, g_h1);    __half* H1 = (__half*)pv;
    cudaGetSymbolAddress(&pv, g_hh);    __half* HH = (__half*)pv;
    cudaGetSymbolAddress(&pv, g_score); __half* SC = (__half*)pv;
    cudaGetSymbolAddress(&pv, g_e1);    __half* E1 = (__half*)pv;
    cudaGetSymbolAddress(&pv, g_eh);    __half* EH = (__half*)pv;
    cudaGetSymbolAddress(&pv, g_stat);  double* ST = (double*)pv;
    cudaGetSymbolAddress(&pv, g_bnsc);  float*  BSC = (float*)pv;
    cudaGetSymbolAddress(&pv, g_bnsh);  float*  BSH = (float*)pv;
    cudaGetSymbolAddress(&pv, g_Bq);    __half* Bq  = (__half*)pv;
    cudaGetSymbolAddress(&pv, g_Bk);    __half* Bk  = (__half*)pv;
    cudaGetSymbolAddress(&pv, g_Bv);    __half* Bv  = (__half*)pv;
    cudaGetSymbolAddress(&pv, g_Be);    __half* Be  = (__half*)pv;
    cudaGetSymbolAddress(&pv, g_BOh);   __half* BOh = (__half*)pv;
    cudaGetSymbolAddress(&pv, g_BOe);   __half* BOe = (__half*)pv;
    cudaGetSymbolAddress(&pv, g_W1th);  __half* W1th = (__half*)pv;
    cudaGetSymbolAddress(&pv, g_W1te);  __half* W1te = (__half*)pv;
    cudaGetSymbolAddress(&pv, g_b2h);   float*  b2h = (float*)pv;
    cudaGetSymbolAddress(&pv, g_b2e);   float*  b2e = (float*)pv;
    cudaGetSymbolAddress(&pv, g_Bf2h);  __half* Bf2h = (__half*)pv;
    cudaGetSymbolAddress(&pv, g_Bf2e);  __half* Bf2e = (__half*)pv;

    __half* RAWh = Q;    // reuse: Q dead after edge_score
    __half* RAWe = SC;   // reuse: score dead after Oe GEMM

    cudaMemsetAsync(SS, 0, sizeof(float) * (size_t)Nn * D);
    cudaMemsetAsync(WV, 0, sizeof(float) * (size_t)Nn * D);
    cudaMemsetAsync(ST, 0, sizeof(double) * 4 * 2 * 128);

    // 0) Weight prep (fp16, transposed)
    wtrans<<<64, 256>>>(Wq,  Bq,  128, 128);
    wtrans<<<64, 256>>>(Wk,  Bk,  128, 128);
    wtrans<<<64, 256>>>(Wv,  Bv,  128, 128);
    wtrans<<<64, 256>>>(We,  Be,  128, 128);
    wtrans<<<64, 256>>>(Ohw, BOh, 128, 128);
    wtrans<<<64, 256>>>(Oew, BOe, 128, 128);
    wtrans<<<128, 256>>>(f2hw, Bf2h, 256, 128);
    wtrans<<<128, 256>>>(f2ew, Bf2e, 256, 128);

    dim3 blk(128);
    dim3 gN (1, (Nn + 127) / 128);
    dim3 gE (1, (Ne + 127) / 128);
    dim3 gN2(2, (Nn + 127) / 128);
    dim3 gE2(2, (Ne + 127) / 128);

    // 1) Projections
    gemm2<128, 0, false, false><<<gN, blk>>>(h, Bq, Q,  128, nullptr, nullptr, 0, nullptr, nullptr, nullptr, Nn);
    gemm2<128, 0, false, false><<<gN, blk>>>(h, Bk, Kk, 128, nullptr, nullptr, 0, nullptr, nullptr, nullptr, Nn);
    gemm2<128, 0, false, false><<<gN, blk>>>(h, Bv, V,  128, nullptr, nullptr, 0, nullptr, nullptr, nullptr, Nn);
    gemm2<128, 0, false, false><<<gE, blk>>>(e, Be, SC, 128, nullptr, nullptr, 0, nullptr, nullptr, nullptr, Ne);

    // 2) Edge attention
    int eblocks = (int)(((size_t)Ne * 32 + 255) / 256);
    edge_score_kernel<<<eblocks, 256>>>(Q, Kk, SC, SS, src, dst, Ne);
    edge_agg_kernel  <<<eblocks, 256>>>(V, SC, SS, WV, src, dst, Ne);

    // 3) Output projections + residual; BN1 stats
    gemm2<128, M_RESP | M_STATS, false, false><<<gN, blk>>>(WV, BOh, H1, 128, Ohb, h, 128, nullptr, nullptr, ST + 0 * 256, Nn);
    gemm2<128, M_RESP | M_STATS, true,  false><<<gE, blk>>>(SC, BOe, E1, 128, Oeb, e, 128, nullptr, nullptr, ST + 1 * 256, Ne);

    bn_finalize_kernel<<<1, 128>>>(ST + 0 * 256, bn1hg, bn1hb, BSC + 0 * 128, BSH + 0 * 128, 1.0 / Nn);
    bn_finalize_kernel<<<1, 128>>>(ST + 1 * 256, bn1eg, bn1eb, BSC + 1 * 128, BSH + 1 * 128, 1.0 / Ne);

    // 3b) Fold BN1 into FFN1 weights/bias (transposed fp16)
    ffn1_prep_t<<<1, 256>>>(f1hw, f1hb, BSC + 0 * 128, BSH + 0 * 128, W1th, b2h);
    ffn1_prep_t<<<1, 256>>>(f1ew, f1eb, BSC + 1 * 128, BSH + 1 * 128, W1te, b2e);

    // 4) FFN layer 1: relu(x @ W1t + b2)
    gemm2<128, M_RELU, true, false><<<gN2, blk>>>(H1, W1th, HH, 256, b2h, nullptr, 0, nullptr, nullptr, nullptr, Nn);
    gemm2<128, M_RELU, true, false><<<gE2, blk>>>(E1, W1te, EH, 256, b2e, nullptr, 0, nullptr, nullptr, nullptr, Ne);

    // 5) FFN layer 2 + residual bn1(x); BN2 stats; raw (fp16) into scratch
    gemm2<256, M_RESBN | M_STATS, true, true><<<gN, blk>>>(HH, Bf2h, RAWh, 128, f2hb, H1, 128, BSC + 0 * 128, BSH + 0 * 128, ST + 2 * 256, Nn);
    gemm2<256, M_RESBN | M_STATS, true, true><<<gE, blk>>>(EH, Bf2e, RAWe, 128, f2eb, E1, 128, BSC + 1 * 128, BSH + 1 * 128, ST + 3 * 256, Ne);

    bn_finalize_kernel<<<1, 128>>>(ST + 2 * 256, bn2hg, bn2hb, BSC + 2 * 128, BSH + 2 * 128, 1.0 / Nn);
    bn_finalize_kernel<<<1, 128>>>(ST + 3 * 256, bn2eg, bn2eb, BSC + 3 * 128, BSH + 3 * 128, 1.0 / Ne);

    // 6) BN2 apply: raw fp16 -> fp32 out
    long n4h = (long)Nn * D / 4;
    long n4e = (long)Ne * D / 4;
    bn_apply_h2f<<<(int)((n4h + 255) / 256), 256>>>(RAWh, out_h, BSC + 2 * 128, BSH + 2 * 128, n4h);
    bn_apply_h2f<<<(int)((n4e + 255) / 256), 256>>>(RAWe, out_e, BSC + 3 * 128, BSH + 3 * 128, n4e);
}

// round 14
// speedup vs baseline: 3.4628x; 1.2082x over previous
#include <cuda_runtime.h>
#include <cuda_fp16.h>
#include <cstdint>

// Problem constants (GraphTransformerLayer: N=50000 nodes, E=800000 edges, D=128, H=8, HD=16)
static constexpr int NNODE = 50000;
static constexpr int NEDGE = 800000;
static constexpr int D     = 128;

// ---------------------------------------------------------------------------
// Scratch (device globals)
// ---------------------------------------------------------------------------
__device__ __half g_Q [NNODE * D];                 // Q proj; later reused as h raw pre-BN2
__device__ __half g_K [NNODE * D];
__device__ __half g_V [NNODE * D];
__device__ float  g_ssum[NNODE * D];
__device__ float  g_wV [NNODE * D];
__device__ __half g_h1 [NNODE * D];
__device__ __half g_hh [NNODE * 2 * D];
__device__ __half g_score[(size_t)NEDGE * D];      // pe->score; later reused as e raw pre-BN2
__device__ __half g_e1 [(size_t)NEDGE * D];
__device__ __half g_eh [(size_t)NEDGE * 2 * D];
__device__ double g_stat[4 * 2 * 128];
__device__ float  g_bnsc[4 * 128];
__device__ float  g_bnsh[4 * 128];
// fp16 transposed weights Bt[n][k]
__device__ __half g_Bq [128 * 128];
__device__ __half g_Bk [128 * 128];
__device__ __half g_Bv [128 * 128];
__device__ __half g_Be [128 * 128];
__device__ __half g_BOh[128 * 128];
__device__ __half g_BOe[128 * 128];
__device__ __half g_W1th[256 * 128];   // FFN1 (BN folded) transposed
__device__ __half g_W1te[256 * 128];
__device__ float  g_b2h[256];
__device__ float  g_b2e[256];
__device__ __half g_Bf2h[128 * 256];
__device__ __half g_Bf2e[128 * 256];

enum { M_RELU = 1, M_RESP = 2, M_RESBN = 4, M_STATS = 8 };

__device__ __forceinline__ void mma_f16(float* c, const uint32_t* a, const uint32_t* b) {
    asm volatile(
        "mma.sync.aligned.m16n8k16.row.col.f32.f16.f16.f32 "
        "{%0,%1,%2,%3},{%4,%5,%6,%7},{%8,%9},{%0,%1,%2,%3};"
        : "+f"(c[0]), "+f"(c[1]), "+f"(c[2]), "+f"(c[3])
        : "r"(a[0]), "r"(a[1]), "r"(a[2]), "r"(a[3]), "r"(b[0]), "r"(b[1]));
}

__device__ __forceinline__ void cp_async16(uint32_t smem, const void* gptr) {
    asm volatile("cp.async.cg.shared.global [%0], [%1], 16;" :: "r"(smem), "l"(gptr));
}
__device__ __forceinline__ void cp_commit() { asm volatile("cp.async.commit_group;"); }
__device__ __forceinline__ void cp_wait0()  { asm volatile("cp.async.wait_group 0;"); }

__device__ __forceinline__ void red_v2(float* p, float a, float b) {
    asm volatile("red.global.add.v2.f32 [%0], {%1, %2};" :: "l"(p), "f"(a), "f"(b) : "memory");
}

// ---------------------------------------------------------------------------
// FP16 tensor-core GEMM: C = A[M,KD] @ Bt^T (+bias)(+res)(+BN-res)(relu)(stats)
// Bt is fp16 [Nout][KD]. Block tile 128x128, 256 threads (8 warps, warp 64x32),
// double-buffered cp.async staging. smem [row][k2] stride 12 (conflict-free).
// ---------------------------------------------------------------------------
template <int KD, int MODE, bool AH, bool RH>
__global__ __launch_bounds__(256, 2) void gemm2(
    const void* __restrict__ Av, const __half* __restrict__ Bt,
    __half* __restrict__ C, int ldc,
    const float* __restrict__ bias,
    const void* __restrict__ residv, int ldr,
    const float* __restrict__ tsc, const float* __restrict__ tsh,
    double* __restrict__ stat, int M)
{
    __shared__ uint32_t As[2][128 * 12];
    __shared__ uint32_t Bs[2][128 * 12];
    __shared__ float red[2][128];

    const int tid  = threadIdx.x;
    const int lane = tid & 31;
    const int warp = tid >> 5;
    const int g    = lane >> 2;
    const int tig  = lane & 3;
    const int wm   = (warp >> 2) * 64;   // 2 warp rows
    const int wn   = (warp & 3) * 32;    // 4 warp cols
    const int m0   = blockIdx.y * 128;
    const int nb   = blockIdx.x * 128;

    const float*  Af = (const float*)Av;
    const __half* Ah = (const __half*)Av;

    uint32_t sA[2], sB[2];
    sA[0] = (uint32_t)__cvta_generic_to_shared(&As[0][0]);
    sA[1] = (uint32_t)__cvta_generic_to_shared(&As[1][0]);
    sB[0] = (uint32_t)__cvta_generic_to_shared(&Bs[0][0]);
    sB[1] = (uint32_t)__cvta_generic_to_shared(&Bs[1][0]);

    float acc[4][4][4];
#pragma unroll
    for (int mt = 0; mt < 4; mt++)
#pragma unroll
        for (int nt = 0; nt < 4; nt++) {
            acc[mt][nt][0] = 0.f; acc[mt][nt][1] = 0.f;
            acc[mt][nt][2] = 0.f; acc[mt][nt][3] = 0.f;
        }

    const int srow = tid >> 1;           // 0..127 (staging row)
    const int shalf = tid & 1;           // 0/1 (k half: 8 halves)
    const uint32_t sOff = (uint32_t)(srow * 48 + shalf * 16);

    // per-thread global pointers
    const __half* brow = Bt + (size_t)(nb + srow) * KD + shalf * 8;
    int gmr = m0 + srow; if (gmr >= M) gmr = M - 1;
    const __half* arowH = Ah + (size_t)gmr * KD + shalf * 8;
    const float*  arowF = Af + (size_t)gmr * KD + shalf * 8;

    float4 aR0, aR1;

    auto stageB = [&](int it, int buf) {
        cp_async16(sB[buf] + sOff, brow + it * 16);
    };
    auto stageAh = [&](int it, int buf) {
        cp_async16(sA[buf] + sOff, arowH + it * 16);
    };
    auto ldgA = [&](int it) {
        const float* p = arowF + it * 16;
        aR0 = *(const float4*)p;
        aR1 = *(const float4*)(p + 4);
    };
    auto stsA = [&](int buf) {
        uint32_t* as = As[buf];
        __half2 h0 = __floats2half2_rn(aR0.x, aR0.y);
        __half2 h1 = __floats2half2_rn(aR0.z, aR0.w);
        __half2 h2 = __floats2half2_rn(aR1.x, aR1.y);
        __half2 h3 = __floats2half2_rn(aR1.z, aR1.w);
        *(uint4*)&as[srow * 12 + shalf * 4] =
            make_uint4(*(uint32_t*)&h0, *(uint32_t*)&h1, *(uint32_t*)&h2, *(uint32_t*)&h3);
    };

    // prologue
    stageB(0, 0);
    if (AH) stageAh(0, 0);
    cp_commit();
    if (!AH) ldgA(0);

    const int nIter = KD / 16;
#pragma unroll 1
    for (int it = 0; it < nIter; ++it) {
        int buf = it & 1;
        if (!AH) stsA(buf);
        cp_wait0();
        __syncthreads();
        if (it + 1 < nIter) {
            stageB(it + 1, buf ^ 1);
            if (AH) stageAh(it + 1, buf ^ 1);
            cp_commit();
            if (!AH) ldgA(it + 1);
        }
        const uint32_t* as = As[buf];
        const uint32_t* bs = Bs[buf];
        uint32_t af[4][4], bf[4][2];
#pragma unroll
        for (int mt = 0; mt < 4; mt++) {
            int r = wm + mt * 16 + g;
            af[mt][0] = as[r * 12 + tig];
            af[mt][1] = as[(r + 8) * 12 + tig];
            af[mt][2] = as[r * 12 + tig + 4];
            af[mt][3] = as[(r + 8) * 12 + tig + 4];
        }
#pragma unroll
        for (int nt = 0; nt < 4; nt++) {
            int cn = wn + nt * 8 + g;
            bf[nt][0] = bs[cn * 12 + tig];
            bf[nt][1] = bs[cn * 12 + tig + 4];
        }
#pragma unroll
        for (int mt = 0; mt < 4; mt++)
#pragma unroll
            for (int nt = 0; nt < 4; nt++)
                mma_f16(acc[mt][nt], af[mt], bf[nt]);
    }

    // ---------------- Epilogue ----------------
    const int cb = wn + (tig << 1);
    float s[4][2], q[4][2];
#pragma unroll
    for (int nt = 0; nt < 4; nt++) { s[nt][0]=0.f; s[nt][1]=0.f; q[nt][0]=0.f; q[nt][1]=0.f; }

#pragma unroll
    for (int mt = 0; mt < 4; mt++) {
        int r0 = m0 + wm + mt * 16 + g;
#pragma unroll
        for (int half = 0; half < 2; half++) {
            int gm = r0 + half * 8;
            if (gm >= M) continue;
#pragma unroll
            for (int nt = 0; nt < 4; nt++) {
                int c = nb + cb + nt * 8;
                float x0 = acc[mt][nt][half * 2 + 0];
                float x1 = acc[mt][nt][half * 2 + 1];
                if (bias) { x0 += bias[c]; x1 += bias[c + 1]; }
                if (MODE & (M_RESP | M_RESBN)) {
                    float2 rr;
                    if (RH) rr = __half22float2(*(const __half2*)((const __half*)residv + (size_t)gm * ldr + c));
                    else    rr = *(const float2*)((const float*)residv + (size_t)gm * ldr + c);
                    if (MODE & M_RESP) { x0 += rr.x; x1 += rr.y; }
                    else {
                        x0 += rr.x * tsc[c] + tsh[c];
                        x1 += rr.y * tsc[c + 1] + tsh[c + 1];
                    }
                }
                if (MODE & M_RELU) { x0 = fmaxf(x0, 0.f); x1 = fmaxf(x1, 0.f); }
                *(__half2*)(C + (size_t)gm * ldc + c) = __floats2half2_rn(x0, x1);
                if (MODE & M_STATS) {
                    s[nt][0] += x0; s[nt][1] += x1;
                    q[nt][0] += x0 * x0; q[nt][1] += x1 * x1;
                }
            }
        }
    }

    if (MODE & M_STATS) {
        __syncthreads();
        if (tid < 128) { red[0][tid] = 0.f; red[1][tid] = 0.f; }
        __syncthreads();
#pragma unroll
        for (int nt = 0; nt < 4; nt++) {
            int c = cb + nt * 8;   // STATS modes have Nout=128, nb=0
            atomicAdd(&red[0][c],     s[nt][0]);
            atomicAdd(&red[0][c + 1], s[nt][1]);
            atomicAdd(&red[1][c],     q[nt][0]);
            atomicAdd(&red[1][c + 1], q[nt][1]);
        }
        __syncthreads();
        if (tid < 128) {
            atomicAdd(&stat[tid],       (double)red[0][tid]);
            atomicAdd(&stat[128 + tid], (double)red[1][tid]);
        }
    }
}

// ---------------------------------------------------------------------------
// Weight prep: fp32 W[K][N] -> fp16 Bt[N][K]
// ---------------------------------------------------------------------------
__global__ void wtrans(const float* __restrict__ W, __half* __restrict__ Bt, int K, int N)
{
    int idx = blockIdx.x * 256 + threadIdx.x;
    if (idx >= K * N) return;
    int n = idx % N, k = idx / N;
    Bt[(size_t)n * K + k] = __float2half(W[idx]);
}

// FFN1 prep: fold BN1 into W1 (transposed fp16) and bias.
__global__ void ffn1_prep_t(const float* __restrict__ W, const float* __restrict__ bias,
                            const float* __restrict__ sc, const float* __restrict__ sh,
                            __half* __restrict__ Wt, float* __restrict__ b2)
{
    int n = threadIdx.x;   // 256 threads
    float a = bias[n];
    for (int k = 0; k < 128; k++) {
        float w = W[k * 256 + n];
        Wt[n * 128 + k] = __float2half(sc[k] * w);
        a += sh[k] * w;
    }
    b2[n] = a;
}

// ---------------------------------------------------------------------------
// Edge kernels (fp16 Q/K/V/score, fp32 accumulators via red.v2)
// ---------------------------------------------------------------------------
__global__ void edge_score_kernel(const __half* __restrict__ Q, const __half* __restrict__ K,
                                  __half* __restrict__ score, float* __restrict__ ssum,
                                  const int* __restrict__ src, const int* __restrict__ dst, int E)
{
    int eid  = (int)((blockIdx.x * (size_t)blockDim.x + threadIdx.x) >> 5);
    int lane = threadIdx.x & 31;
    if (eid >= E) return;
    int s = src[eid], d = dst[eid];
    uint2 kr = *(const uint2*)(K + (size_t)s * D + (lane << 2));
    uint2 qr = *(const uint2*)(Q + (size_t)d * D + (lane << 2));
    float2 k0 = __half22float2(*(__half2*)&kr.x), k1 = __half22float2(*(__half2*)&kr.y);
    float2 q0 = __half22float2(*(__half2*)&qr.x), q1 = __half22float2(*(__half2*)&qr.y);
    float p = k0.x*q0.x + k0.y*q0.y + k1.x*q1.x + k1.y*q1.y;
    p += __shfl_xor_sync(0xffffffffu, p, 1);
    p += __shfl_xor_sync(0xffffffffu, p, 2);   // dot over 16 channels of this head
    float dt = p * 0.25f;                      // / sqrt(HD=16)
    size_t off = (size_t)eid * D + (lane << 2);
    uint2 pr = *(const uint2*)(score + off);
    float2 p0 = __half22float2(*(__half2*)&pr.x), p1 = __half22float2(*(__half2*)&pr.y);
    __half2 h0 = __floats2half2_rn(p0.x + dt, p0.y + dt);
    __half2 h1 = __floats2half2_rn(p1.x + dt, p1.y + dt);
    *(uint2*)(score + off) = make_uint2(*(uint32_t*)&h0, *(uint32_t*)&h1);
    float2 f0 = __half22float2(h0), f1 = __half22float2(h1);
    float* sp = ssum + (size_t)d * D + (lane << 2);
    red_v2(sp + 0, __expf(f0.x), __expf(f0.y));
    red_v2(sp + 2, __expf(f1.x), __expf(f1.y));
}

__global__ void edge_agg_kernel(const __half* __restrict__ V, const __half* __restrict__ score,
                                const float* __restrict__ ssum, float* __restrict__ wV,
                                const int* __restrict__ src, const int* __restrict__ dst, int E)
{
    int eid  = (int)((blockIdx.x * (size_t)blockDim.x + threadIdx.x) >> 5);
    int lane = threadIdx.x & 31;
    if (eid >= E) return;
    int s = src[eid], d = dst[eid];
    size_t off = (size_t)eid * D + (lane << 2);
    uint2 sr = *(const uint2*)(score + off);
    float2 s0 = __half22float2(*(__half2*)&sr.x), s1 = __half22float2(*(__half2*)&sr.y);
    float4 ss = *(const float4*)(ssum + (size_t)d * D + (lane << 2));
    uint2 vr = *(const uint2*)(V + (size_t)s * D + (lane << 2));
    float2 v0 = __half22float2(*(__half2*)&vr.x), v1 = __half22float2(*(__half2*)&vr.y);
    float* wp = wV + (size_t)d * D + (lane << 2);
    red_v2(wp + 0, __expf(s0.x) / ss.x * v0.x, __expf(s0.y) / ss.y * v0.y);
    red_v2(wp + 2, __expf(s1.x) / ss.z * v1.x, __expf(s1.y) / ss.w * v1.y);
}

// ---------------------------------------------------------------------------
// BN finalize + apply (half raw -> fp32 out)
// ---------------------------------------------------------------------------
__global__ void bn_finalize_kernel(const double* __restrict__ stat,
                                   const float* __restrict__ gamma, const float* __restrict__ beta,
                                   float* __restrict__ osc, float* __restrict__ osh, double invM)
{
    int c = threadIdx.x;
    float mu  = (float)(stat[c] * invM);
    float var = (float)(stat[128 + c] * invM) - mu * mu;
    float rs  = rsqrtf(var + 1e-5f);
    float scv = gamma[c] * rs;
    osc[c] = scv;
    osh[c] = beta[c] - mu * scv;
}

__global__ void bn_apply_h2f(const __half* __restrict__ raw, float* __restrict__ out,
                             const float* __restrict__ sc, const float* __restrict__ sh, long n4)
{
    long i = (long)blockIdx.x * blockDim.x + threadIdx.x;
    if (i >= n4) return;
    uint2 r = ((const uint2*)raw)[i];
    float2 a = __half22float2(*(__half2*)&r.x);
    float2 b = __half22float2(*(__half2*)&r.y);
    int c = (int)(i & 31) << 2;
    float4 v;
    v.x = a.x * sc[c+0] + sh[c+0];
    v.y = a.y * sc[c+1] + sh[c+1];
    v.z = b.x * sc[c+2] + sh[c+2];
    v.w = b.y * sc[c+3] + sh[c+3];
    ((float4*)out)[i] = v;
}

// ---------------------------------------------------------------------------
// Launch
// ---------------------------------------------------------------------------
extern "C" void kernel_launch(void* const* d_in, const int* in_sizes, int n_in,
                              void* d_out, int out_size)
{
    const float* h    = (const float*)d_in[0];
    const float* e    = (const float*)d_in[1];
    const int*   src  = (const int*)d_in[2];
    const int*   dst  = (const int*)d_in[3];
    const float* Wq   = (const float*)d_in[4];
    const float* Wk   = (const float*)d_in[5];
    const float* Wv   = (const float*)d_in[6];
    const float* We   = (const float*)d_in[7];
    const float* Ohw  = (const float*)d_in[8];
    const float* Ohb  = (const float*)d_in[9];
    const float* Oew  = (const float*)d_in[10];
    const float* Oeb  = (const float*)d_in[11];
    const float* bn1hg = (const float*)d_in[12];
    const float* bn1hb = (const float*)d_in[13];
    const float* bn1eg = (const float*)d_in[14];
    const float* bn1eb = (const float*)d_in[15];
    const float* bn2hg = (const float*)d_in[16];
    const float* bn2hb = (const float*)d_in[17];
    const float* bn2eg = (const float*)d_in[18];
    const float* bn2eb = (const float*)d_in[19];
    const float* f1hw = (const float*)d_in[20];
    const float* f1hb = (const float*)d_in[21];
    const float* f2hw = (const float*)d_in[22];
    const float* f2hb = (const float*)d_in[23];
    const float* f1ew = (const float*)d_in[24];
    const float* f1eb = (const float*)d_in[25];
    const float* f2ew = (const float*)d_in[26];
    const float* f2eb = (const float*)d_in[27];

    const int Nn = in_sizes[0] / D;   // 50000
    const int Ne = in_sizes[2];       // 800000

    float* out   = (float*)d_out;
    float* out_h = out;
    float* out_e = out + (size_t)Nn * D;

    void* pv;
    cudaGetSymbolAddress(&pv, g_Q);     __half* Q  = (__half*)pv;
    cudaGetSymbolAddress(&pv, g_K);     __half* Kk = (__half*)pv;
    cudaGetSymbolAddress(&pv, g_V);     __half* V  = (__half*)pv;
    cudaGetSymbolAddress(&pv, g_ssum);  float*  SS = (float*)pv;
    cudaGetSymbolAddress(&pv, g_wV);    float*  WV = (float*)pv;
    cudaGetSymbolAddress(&pv, g_h1);    __half* H1 = (__half*)pv;
    cudaGetSymbolAddress(&pv, g_hh);    __half* HH = (__half*)pv;
    cudaGetSymbolAddress(&pv, g_score); __half* SC = (__half*)pv;
    cudaGetSymbolAddress(&pv, g_e1);    __half* E1 = (__half*)pv;
    cudaGetSymbolAddress(&pv, g_eh);    __half* EH = (__half*)pv;
    cudaGetSymbolAddress(&pv, g_stat);  double* ST = (double*)pv;
    cudaGetSymbolAddress(&pv, g_bnsc);  float*  BSC = (float*)pv;
    cudaGetSymbolAddress(&pv, g_bnsh);  float*  BSH = (float*)pv;
    cudaGetSymbolAddress(&pv, g_Bq);    __half* Bq  = (__half*)pv;
    cudaGetSymbolAddress(&pv, g_Bk);    __half* Bk  = (__half*)pv;
    cudaGetSymbolAddress(&pv, g_Bv);    __half* Bv  = (__half*)pv;
    cudaGetSymbolAddress(&pv, g_Be);    __half* Be  = (__half*)pv;
    cudaGetSymbolAddress(&pv, g_BOh);   __half* BOh = (__half*)pv;
    cudaGetSymbolAddress(&pv, g_BOe);   __half* BOe = (__half*)pv;
    cudaGetSymbolAddress(&pv, g_W1th);  __half* W1th = (__half*)pv;
    cudaGetSymbolAddress(&pv, g_W1te);  __half* W1te = (__half*)pv;
    cudaGetSymbolAddress(&pv, g_b2h);   float*  b2h = (float*)pv;
    cudaGetSymbolAddress(&pv, g_b2e);   float*  b2e = (float*)pv;
    cudaGetSymbolAddress(&pv, g_Bf2h);  __half* Bf2h = (__half*)pv;
    cudaGetSymbolAddress(&pv, g_Bf2e);  __half* Bf2e = (__half*)pv;

    __half* RAWh = Q;    // reuse: Q dead after edge_score
    __half* RAWe = SC;   // reuse: score dead after Oe GEMM

    cudaMemsetAsync(SS, 0, sizeof(float) * (size_t)Nn * D);
    cudaMemsetAsync(WV, 0, sizeof(float) * (size_t)Nn * D);
    cudaMemsetAsync(ST, 0, sizeof(double) * 4 * 2 * 128);

    // 0) Weight prep (fp16, transposed)
    wtrans<<<64, 256>>>(Wq,  Bq,  128, 128);
    wtrans<<<64, 256>>>(Wk,  Bk,  128, 128);
    wtrans<<<64, 256>>>(Wv,  Bv,  128, 128);
    wtrans<<<64, 256>>>(We,  Be,  128, 128);
    wtrans<<<64, 256>>>(Ohw, BOh, 128, 128);
    wtrans<<<64, 256>>>(Oew, BOe, 128, 128);
    wtrans<<<128, 256>>>(f2hw, Bf2h, 256, 128);
    wtrans<<<128, 256>>>(f2ew, Bf2e, 256, 128);

    dim3 blk(256);
    dim3 gN (1, (Nn + 127) / 128);
    dim3 gE (1, (Ne + 127) / 128);
    dim3 gN2(2, (Nn + 127) / 128);
    dim3 gE2(2, (Ne + 127) / 128);

    // 1) Projections
    gemm2<128, 0, false, false><<<gN, blk>>>(h, Bq, Q,  128, nullptr, nullptr, 0, nullptr, nullptr, nullptr, Nn);
    gemm2<128, 0, false, false><<<gN, blk>>>(h, Bk, Kk, 128, nullptr, nullptr, 0, nullptr, nullptr, nullptr, Nn);
    gemm2<128, 0, false, false><<<gN, blk>>>(h, Bv, V,  128, nullptr, nullptr, 0, nullptr, nullptr, nullptr, Nn);
    gemm2<128, 0, false, false><<<gE, blk>>>(e, Be, SC, 128, nullptr, nullptr, 0, nullptr, nullptr, nullptr, Ne);

    // 2) Edge attention
    int eblocks = (int)(((size_t)Ne * 32 + 255) / 256);
    edge_score_kernel<<<eblocks, 256>>>(Q, Kk, SC, SS, src, dst, Ne);
    edge_agg_kernel  <<<eblocks, 256>>>(V, SC, SS, WV, src, dst, Ne);

    // 3) Output projections + residual; BN1 stats
    gemm2<128, M_RESP | M_STATS, false, false><<<gN, blk>>>(WV, BOh, H1, 128, Ohb, h, 128, nullptr, nullptr, ST + 0 * 256, Nn);
    gemm2<128, M_RESP | M_STATS, true,  false><<<gE, blk>>>(SC, BOe, E1, 128, Oeb, e, 128, nullptr, nullptr, ST + 1 * 256, Ne);

    bn_finalize_kernel<<<1, 128>>>(ST + 0 * 256, bn1hg, bn1hb, BSC + 0 * 128, BSH + 0 * 128, 1.0 / Nn);
    bn_finalize_kernel<<<1, 128>>>(ST + 1 * 256, bn1eg, bn1eb, BSC + 1 * 128, BSH + 1 * 128, 1.0 / Ne);

    // 3b) Fold BN1 into FFN1 weights/bias (transposed fp16)
    ffn1_prep_t<<<1, 256>>>(f1hw, f1hb, BSC + 0 * 128, BSH + 0 * 128, W1th, b2h);
    ffn1_prep_t<<<1, 256>>>(f1ew, f1eb, BSC + 1 * 128, BSH + 1 * 128, W1te, b2e);

    // 4) FFN layer 1: relu(x @ W1t + b2)
    gemm2<128, M_RELU, true, false><<<gN2, blk>>>(H1, W1th, HH, 256, b2h, nullptr, 0, nullptr, nullptr, nullptr, Nn);
    gemm2<128, M_RELU, true, false><<<gE2, blk>>>(E1, W1te, EH, 256, b2e, nullptr, 0, nullptr, nullptr, nullptr, Ne);

    // 5) FFN layer 2 + residual bn1(x); BN2 stats; raw (fp16) into scratch
    gemm2<256, M_RESBN | M_STATS, true, true><<<gN, blk>>>(HH, Bf2h, RAWh, 128, f2hb, H1, 128, BSC + 0 * 128, BSH + 0 * 128, ST + 2 * 256, Nn);
    gemm2<256, M_RESBN | M_STATS, true, true><<<gE, blk>>>(EH, Bf2e, RAWe, 128, f2eb, E1, 128, BSC + 1 * 128, BSH + 1 * 128, ST + 3 * 256, Ne);

    bn_finalize_kernel<<<1, 128>>>(ST + 2 * 256, bn2hg, bn2hb, BSC + 2 * 128, BSH + 2 * 128, 1.0 / Nn);
    bn_finalize_kernel<<<1, 128>>>(ST + 3 * 256, bn2eg, bn2eb, BSC + 3 * 128, BSH + 3 * 128, 1.0 / Ne);

    // 6) BN2 apply: raw fp16 -> fp32 out
    long n4h = (long)Nn * D / 4;
    long n4e = (long)Ne * D / 4;
    bn_apply_h2f<<<(int)((n4h + 255) / 256), 256>>>(RAWh, out_h, BSC + 2 * 128, BSH + 2 * 128, n4h);
    bn_apply_h2f<<<(int)((n4e + 255) / 256), 256>>>(RAWe, out_e, BSC + 3 * 128, BSH + 3 * 128, n4e);
}